// round 1
// baseline (speedup 1.0000x reference)
#include <cuda_runtime.h>
#include <math.h>

// Problem constants (from dataset: B=2048, C=16384, D=128)
#define BDIM_MAX 2048
#define CDIM_MAX 16384
#define DDIM     128
#define NTAB     4096
#define VF       63.0f     // v = D/2 - 1
#define V2F      3969.0f   // v^2

// -------- device scratch (no allocations allowed) --------
__device__ float  g_Q[CDIM_MAX];       // k2^2
__device__ float  g_alpha[CDIM_MAX];   // 2*k2/||w||
__device__ float  g_e[CDIM_MAX];       // f(v^2 + k2^2)
__device__ float  g_P[BDIM_MAX];       // v^2 + k1^2
__device__ float  g_beta[BDIM_MAX];    // k1/||feat||
__device__ float  g_xg[BDIM_MAX];      // gathered x at class y_b
__device__ float  g_partial[BDIM_MAX * 128];
__device__ float2 g_tab[NTAB];
__device__ int    g_k1max_i, g_k2max_i;
__device__ float  g_tlo, g_invh;

// ---------------- helpers ----------------
__device__ __forceinline__ float f_exact(float t) {
    float s = sqrtf(t);
    return s - VF * logf(VF + s) - 0.5f * logf(s);
}

// exp(x) without MUFU: 2^(x*log2e) via round-split + degree-5 Taylor of 2^f
__device__ __forceinline__ float exp_fast(float x) {
    x = fminf(fmaxf(x, -87.0f), 80.0f);
    float y = x * 1.4426950408889634f;
    float r = y + 12582912.0f;                    // 1.5*2^23 magic
    int   m = __float_as_int(r) - 0x4B400000;     // round(y)
    float f = y - (r - 12582912.0f);              // frac in [-0.5, 0.5]
    float p = 1.33335581e-3f;
    p = fmaf(p, f, 9.61812910e-3f);
    p = fmaf(p, f, 5.55041086e-2f);
    p = fmaf(p, f, 2.40226507e-1f);
    p = fmaf(p, f, 6.93147181e-1f);
    p = fmaf(p, f, 1.0f);
    return __int_as_float(__float_as_int(p) + (m << 23));
}

// ---------------- prep kernels ----------------
__global__ void init_minmax() { g_k1max_i = 0; g_k2max_i = 0; }

// one warp per class: norm, k2, Q, alpha, e
__global__ void class_prep(const float* __restrict__ W, int C) {
    int c = blockIdx.x * 8 + (threadIdx.x >> 5);
    int lane = threadIdx.x & 31;
    if (c >= C) return;
    float4 w = ((const float4*)W)[c * 32 + lane];
    float ss = w.x*w.x + w.y*w.y + w.z*w.z + w.w*w.w;
    #pragma unroll
    for (int o = 16; o; o >>= 1) ss += __shfl_xor_sync(0xffffffffu, ss, o);
    if (lane == 0) {
        float nw = sqrtf(ss);
        float k2 = fmaxf(nw, 1.0f) * 10.0f;       // INV_TEMP = 10
        g_Q[c]     = k2 * k2;
        g_alpha[c] = 2.0f * k2 / nw;
        g_e[c]     = f_exact(V2F + k2 * k2);
        atomicMax(&g_k2max_i, __float_as_int(k2));
    }
}

// one block per batch row: norm, k1, P, beta, exact gathered term
__global__ void batch_prep(const float* __restrict__ F, const float* __restrict__ W,
                           const float* __restrict__ unc, const int* __restrict__ y) {
    __shared__ float sred[8];
    int b = blockIdx.x;
    int t = threadIdx.x;  // 128 threads
    int cls = y[b];
    float fv = F[b * DDIM + t];
    float wv = W[cls * DDIM + t];
    float ss = fv * fv;
    float dp = fv * wv;
    #pragma unroll
    for (int o = 16; o; o >>= 1) {
        ss += __shfl_xor_sync(0xffffffffu, ss, o);
        dp += __shfl_xor_sync(0xffffffffu, dp, o);
    }
    int w = t >> 5, lane = t & 31;
    if (lane == 0) { sred[w] = ss; sred[4 + w] = dp; }
    __syncthreads();
    if (t == 0) {
        float sst = sred[0] + sred[1] + sred[2] + sred[3];
        float dpt = sred[4] + sred[5] + sred[6] + sred[7];
        float nb = sqrtf(sst);
        float k1 = 1.0f / unc[b];
        float P  = V2F + k1 * k1;
        float be = k1 / nb;
        g_P[b] = P; g_beta[b] = be;
        float t3 = fmaf(be * g_alpha[cls], dpt, P + g_Q[cls]);
        g_xg[b] = f_exact(t3) - g_e[cls];
        atomicMax(&g_k1max_i, __float_as_int(k1));
    }
}

// PWL table for f(t) over t in [v^2, v^2 + (k1max+k2max)^2], built in double
__global__ void build_table() {
    int i = blockIdx.x * blockDim.x + threadIdx.x;
    if (i >= NTAB) return;
    double k1m = (double)__int_as_float(g_k1max_i);
    double k2m = (double)__int_as_float(g_k2max_i);
    double tlo = 3969.0;
    double km  = k1m + k2m;
    double thi = tlo + km * km + 16.0;
    double h   = (thi - tlo) / (double)(NTAB - 1);
    double t0 = tlo + h * (double)i;
    double t1 = t0 + h;
    double s0 = sqrt(t0), s1 = sqrt(t1);
    double f0 = s0 - 63.0 * log(63.0 + s0) - 0.5 * log(s0);
    double f1 = s1 - 63.0 * log(63.0 + s1) - 0.5 * log(s1);
    g_tab[i] = make_float2((float)f0, (float)(f1 - f0));
    if (i == 0) { g_tlo = 3969.0f; g_invh = (float)(1.0 / h); }
}

// ---------------- fused GEMM + softmax-sum ----------------
// CTA tile 128(b) x 128(c), K = 128 (full D in smem), 256 threads, 8x8/thread.
// Both tiles stored k-major (as in global) with XOR swizzle on float4 columns.
#define SMEM_BYTES (4096*16 + 4096*16 + 4096*8)   // As + Ws + table = 160 KB

__global__ void __launch_bounds__(256, 1)
fused_kernel(const float* __restrict__ F, const float* __restrict__ W) {
    extern __shared__ float smem_raw[];
    float4* As4 = (float4*)smem_raw;          // 4096 float4 (128 rows x 32)
    float4* Ws4 = As4 + 4096;                 // 4096 float4
    float2* tab = (float2*)(Ws4 + 4096);      // 4096 float2

    const int tid = threadIdx.x;
    const int bx = blockIdx.x, by = blockIdx.y;

    // stage f-table into smem (as float4 copies)
    {
        const float4* src = (const float4*)g_tab;
        float4* dst = (float4*)tab;
        #pragma unroll
        for (int i = 0; i < 8; ++i) dst[tid + 256 * i] = src[tid + 256 * i];
    }
    // stage A (features rows) and B (classifier rows), swizzled
    {
        const float4* gA = (const float4*)F + (size_t)by * 128 * 32;
        const float4* gW = (const float4*)W + (size_t)bx * 128 * 32;
        #pragma unroll
        for (int it = 0; it < 16; ++it) {
            int g = it * 256 + tid;
            int row = g >> 5, f4c = g & 31;
            int sw = (row ^ (row >> 3)) & 7;
            As4[row * 32 + (f4c ^ sw)] = gA[g];
        }
        #pragma unroll
        for (int it = 0; it < 16; ++it) {
            int g = it * 256 + tid;
            int row = g >> 5, f4c = g & 31;
            int sw = (row ^ (row >> 3)) & 7;
            Ws4[row * 32 + (f4c ^ sw)] = gW[g];
        }
    }
    __syncthreads();

    const int tx = tid & 15, ty = tid >> 4;
    const int r0 = ty * 8, c0 = tx * 8;

    float acc[8][8];
    #pragma unroll
    for (int i = 0; i < 8; ++i)
        #pragma unroll
        for (int j = 0; j < 8; ++j) acc[i][j] = 0.0f;

    int swa[8], swb[8];
    #pragma unroll
    for (int i = 0; i < 8; ++i) {
        int ra = r0 + i, rb = c0 + i;
        swa[i] = (ra ^ (ra >> 3)) & 7;
        swb[i] = (rb ^ (rb >> 3)) & 7;
    }

    #pragma unroll 2
    for (int kq = 0; kq < 32; ++kq) {
        float4 av[8], bv[8];
        #pragma unroll
        for (int i = 0; i < 8; ++i) av[i] = As4[(r0 + i) * 32 + (kq ^ swa[i])];
        #pragma unroll
        for (int j = 0; j < 8; ++j) bv[j] = Ws4[(c0 + j) * 32 + (kq ^ swb[j])];
        #pragma unroll
        for (int i = 0; i < 8; ++i)
            #pragma unroll
            for (int j = 0; j < 8; ++j) {
                acc[i][j] = fmaf(av[i].x, bv[j].x, acc[i][j]);
                acc[i][j] = fmaf(av[i].y, bv[j].y, acc[i][j]);
                acc[i][j] = fmaf(av[i].z, bv[j].z, acc[i][j]);
                acc[i][j] = fmaf(av[i].w, bv[j].w, acc[i][j]);
            }
    }

    // epilogue: t3 -> f via table -> exp -> row sums
    const float tlo = g_tlo, invh = g_invh;
    float Pr[8], be[8], Qa[8], al[8], ej[8];
    #pragma unroll
    for (int i = 0; i < 8; ++i) {
        int r = by * 128 + r0 + i;
        Pr[i] = g_P[r]; be[i] = g_beta[r];
    }
    #pragma unroll
    for (int j = 0; j < 8; ++j) {
        int c = bx * 128 + c0 + j;
        Qa[j] = g_Q[c]; al[j] = g_alpha[c]; ej[j] = g_e[c];
    }

    #pragma unroll
    for (int i = 0; i < 8; ++i) {
        float rsum = 0.0f;
        #pragma unroll
        for (int j = 0; j < 8; ++j) {
            float t = fmaf(be[i] * al[j], acc[i][j], Pr[i] + Qa[j]);
            float u = (t - tlo) * invh;
            u = fminf(fmaxf(u, 0.0f), (float)(NTAB - 2) + 0.999f);
            int   k  = (int)u;
            float fr = u - (float)k;
            float2 te = tab[k];
            float x = fmaf(fr, te.y, te.x) - ej[j];
            rsum += exp_fast(x);
        }
        // reduce across tx (16 lanes of same ty within warp)
        rsum += __shfl_xor_sync(0xffffffffu, rsum, 1);
        rsum += __shfl_xor_sync(0xffffffffu, rsum, 2);
        rsum += __shfl_xor_sync(0xffffffffu, rsum, 4);
        rsum += __shfl_xor_sync(0xffffffffu, rsum, 8);
        if (tx == 0)
            g_partial[(size_t)(by * 128 + r0 + i) * gridDim.x + bx] = rsum;
    }
}

// ---------------- final reduction ----------------
__global__ void finalize(float* __restrict__ out, int B, int nbx) {
    __shared__ float sred[32];
    int t = threadIdx.x;
    float local = 0.0f;
    for (int r = t; r < B; r += blockDim.x) {
        const float4* p4 = (const float4*)(g_partial + (size_t)r * nbx);
        float S = 0.0f;
        for (int q = 0; q < nbx / 4; ++q) {
            float4 v = p4[q];
            S += (v.x + v.y) + (v.z + v.w);
        }
        local += logf(S) - g_xg[r];
    }
    #pragma unroll
    for (int o = 16; o; o >>= 1) local += __shfl_xor_sync(0xffffffffu, local, o);
    if ((t & 31) == 0) sred[t >> 5] = local;
    __syncthreads();
    if (t < 32) {
        float v = (t < (int)(blockDim.x >> 5)) ? sred[t] : 0.0f;
        #pragma unroll
        for (int o = 16; o; o >>= 1) v += __shfl_xor_sync(0xffffffffu, v, o);
        if (t == 0) out[0] = v / (float)B;
    }
}

// ---------------- launch ----------------
extern "C" void kernel_launch(void* const* d_in, const int* in_sizes, int n_in,
                              void* d_out, int out_size) {
    // inputs: [0]=pred (UNUSED), [1]=unc, [2]=y, [3]=features, [4]=classifier_weight
    const float* unc = (const float*)d_in[1];
    const int*   y   = (const int*)d_in[2];
    const float* F   = (const float*)d_in[3];
    const float* W   = (const float*)d_in[4];
    int B = in_sizes[1];
    int C = in_sizes[4] / DDIM;

    init_minmax<<<1, 1>>>();
    class_prep<<<C / 8, 256>>>(W, C);
    batch_prep<<<B, 128>>>(F, W, unc, y);
    build_table<<<NTAB / 256, 256>>>();

    cudaFuncSetAttribute(fused_kernel, cudaFuncAttributeMaxDynamicSharedMemorySize, SMEM_BYTES);
    dim3 grid(C / 128, B / 128);
    fused_kernel<<<grid, 256, SMEM_BYTES>>>(F, W);

    finalize<<<1, 1024>>>((float*)d_out, B, C / 128);
}

// round 4
// speedup vs baseline: 1.6182x; 1.6182x over previous
#include <cuda_runtime.h>
#include <math.h>
#include <cstdint>

// Problem constants: B=2048, C=16384, D=128
#define BDIM_MAX 2048
#define CDIM_MAX 16384
#define DDIM     128
#define NTAB     4096
#define VF       63.0f
#define V2F      3969.0f
#define L2E      1.4426950408889634f
#define MAGIC    12582912.0f           // 1.5 * 2^23

// -------- device scratch --------
__device__ float  g_Fn[BDIM_MAX * DDIM];     // normalized features (tf32-rounded)
__device__ float  g_Wn[CDIM_MAX * DDIM];     // normalized classifier rows (tf32-rounded)
__device__ float  g_kq[CDIM_MAX];            // k2 * invh
__device__ float  g_Qh[CDIM_MAX];            // (k2^2 + v^2 - tlo2) * invh
__device__ float  g_ez[CDIM_MAX];            // -e * L2E  (exact, NOT magic-folded)
__device__ float  g_Pu[BDIM_MAX];            // k1^2 * invh
__device__ float  g_2k1[BDIM_MAX];           // 2*k1
__device__ float  g_xg[BDIM_MAX];            // gathered x at class y_b (exact)
__device__ float  g_partial[BDIM_MAX * 256];
__device__ float2 g_tab[NTAB];
__device__ int    g_k1max_i, g_k2max_i;
__device__ float  g_invh;

// ---------------- helpers ----------------
__device__ __forceinline__ float f_exact(float t) {
    float s = sqrtf(t);
    return s - VF * logf(VF + s) - 0.5f * logf(s);
}

__device__ __forceinline__ float to_tf32(float x) {
    uint32_t r;
    asm("cvt.rna.tf32.f32 %0, %1;" : "=r"(r) : "f"(x));
    return __uint_as_float(r);
}

__device__ __forceinline__ void mma_tf32(float* d, const uint32_t* a, const uint32_t* b) {
    asm volatile(
        "mma.sync.aligned.m16n8k8.row.col.f32.tf32.tf32.f32 "
        "{%0,%1,%2,%3}, {%4,%5,%6,%7}, {%8,%9}, {%0,%1,%2,%3};\n"
        : "+f"(d[0]), "+f"(d[1]), "+f"(d[2]), "+f"(d[3])
        : "r"(a[0]), "r"(a[1]), "r"(a[2]), "r"(a[3]), "r"(b[0]), "r"(b[1]));
}

// ---------------- prep kernels ----------------
__global__ void init_minmax() { g_k1max_i = 0; g_k2max_i = 0; }

// one warp per class: normalize row (tf32-rounded), stash raw k2
__global__ void class_norm(const float* __restrict__ W, int C) {
    int c = blockIdx.x * 8 + (threadIdx.x >> 5);
    int lane = threadIdx.x & 31;
    if (c >= C) return;
    float4 w = ((const float4*)W)[c * 32 + lane];
    float ss = w.x*w.x + w.y*w.y + w.z*w.z + w.w*w.w;
    #pragma unroll
    for (int o = 16; o; o >>= 1) ss += __shfl_xor_sync(0xffffffffu, ss, o);
    float nw = sqrtf(ss);
    float inv = 1.0f / nw;
    ((float4*)g_Wn)[c * 32 + lane] = make_float4(
        to_tf32(w.x*inv), to_tf32(w.y*inv), to_tf32(w.z*inv), to_tf32(w.w*inv));
    if (lane == 0) {
        float k2 = fmaxf(nw, 1.0f) * 10.0f;      // INV_TEMP = 10
        g_kq[c] = k2;                             // temp raw k2 (rescaled later)
        atomicMax(&g_k2max_i, __float_as_int(k2));
    }
}

// one block (128 thr) per batch row
__global__ void batch_prep(const float* __restrict__ F, const float* __restrict__ W,
                           const float* __restrict__ unc, const int* __restrict__ y) {
    __shared__ float sred[12];
    __shared__ float s_invnb;
    int b = blockIdx.x;
    int t = threadIdx.x;
    int cls = y[b];
    float fv = F[b * DDIM + t];
    float wv = W[cls * DDIM + t];
    float ssf = fv * fv, ssw = wv * wv, dp = fv * wv;
    #pragma unroll
    for (int o = 16; o; o >>= 1) {
        ssf += __shfl_xor_sync(0xffffffffu, ssf, o);
        ssw += __shfl_xor_sync(0xffffffffu, ssw, o);
        dp  += __shfl_xor_sync(0xffffffffu, dp,  o);
    }
    int w = t >> 5, lane = t & 31;
    if (lane == 0) { sred[w] = ssf; sred[4 + w] = ssw; sred[8 + w] = dp; }
    __syncthreads();
    if (t == 0) {
        float sf = sred[0] + sred[1] + sred[2] + sred[3];
        float sw = sred[4] + sred[5] + sred[6] + sred[7];
        float dt = sred[8] + sred[9] + sred[10] + sred[11];
        float nb = sqrtf(sf), nw = sqrtf(sw);
        float k1 = 1.0f / unc[b];
        g_2k1[b] = 2.0f * k1;
        g_Pu[b]  = k1 * k1;                      // raw; rescaled later
        float k2 = fmaxf(nw, 1.0f) * 10.0f;
        float dotn = dt / (nb * nw);
        float t3 = V2F + k1*k1 + k2*k2 + 2.0f*k1*k2*dotn;
        g_xg[b] = f_exact(t3) - f_exact(V2F + k2 * k2);
        atomicMax(&g_k1max_i, __float_as_int(k1));
        s_invnb = 1.0f / nb;
    }
    __syncthreads();
    g_Fn[b * DDIM + t] = to_tf32(fv * s_invnb);
}

// PWL table; node grid starts one bin BELOW v^2 so u >= 1 (no lower clamp).
// Lookup uses k = round(u), fr in [-0.5, 0.5].
__global__ void build_table() {
    int i = blockIdx.x * blockDim.x + threadIdx.x;
    if (i >= NTAB) return;
    double k1m = (double)__int_as_float(g_k1max_i);
    double k2m = (double)__int_as_float(g_k2max_i);
    double tlo = 3969.0;
    double km  = k1m + k2m;
    double thi = tlo + km * km + 16.0;
    double h   = (thi - tlo) / (double)(NTAB - 2);
    double t0  = (tlo - h) + h * (double)i;
    double t1  = t0 + h;
    double s0 = sqrt(t0), s1 = sqrt(t1);
    double f0 = s0 - 63.0 * log(63.0 + s0) - 0.5 * log(s0);
    double f1 = s1 - 63.0 * log(63.0 + s1) - 0.5 * log(s1);
    g_tab[i] = make_float2((float)(f0 * (double)L2E), (float)((f1 - f0) * (double)L2E));
    if (i == 0) g_invh = (float)(1.0 / h);
}

// finalize per-class / per-row params once invh is known
__global__ void class_params(int C) {
    int c = blockIdx.x * 256 + threadIdx.x;
    if (c >= C) return;
    float k2 = g_kq[c];
    float invh = g_invh;
    float tlo2 = 3969.0f - 1.0f / invh;
    g_kq[c] = k2 * invh;
    g_Qh[c] = (V2F + k2 * k2 - tlo2) * invh;
    g_ez[c] = -f_exact(V2F + k2 * k2) * L2E;
}
__global__ void batch_params(int B) {
    int b = blockIdx.x * 256 + threadIdx.x;
    if (b >= B) return;
    g_Pu[b] = g_Pu[b] * g_invh;
}

// ---------------- fused HMMA tf32 GEMM + epilogue ----------------
// CTA: 256 threads (8 warps), tile 128(b) x 128(c), K=128.
// Warp tile 32x64: warp_m = wid>>1 (4), warp_n = wid&1 (2).
#define LDST      132
#define OFF_KQ    0                       // 128 floats
#define OFF_QH    512
#define OFF_EZ    1024
#define OFF_TAB   1536                    // 4096 float2 = 32768
#define OFF_A     34304                   // 128*132*4 = 67584
#define OFF_B     (34304 + 67584)
#define SMEM_TOTAL (OFF_B + 67584)        // 169472

__global__ void __launch_bounds__(256, 1)
fused_hmma(const float* __restrict__ Fn, const float* __restrict__ Wn) {
    extern __shared__ char smem[];
    float* As  = (float*)(smem + OFF_A);
    float* Bs  = (float*)(smem + OFF_B);
    float* kqS = (float*)(smem + OFF_KQ);
    float* QhS = (float*)(smem + OFF_QH);
    float* ezS = (float*)(smem + OFF_EZ);
    const float2* tab = (const float2*)(smem + OFF_TAB);

    const int tid = threadIdx.x;
    const int bx = blockIdx.x, by = blockIdx.y;
    const int wid = tid >> 5, lane = tid & 31;

    // stage per-class params (ez exact — no magic folding!)
    if (tid < 128) {
        int c = bx * 128 + tid;
        kqS[tid] = g_kq[c];
        QhS[tid] = g_Qh[c];
        ezS[tid] = g_ez[c];
    }
    // stage table
    {
        const float4* src = (const float4*)g_tab;
        float4* dst = (float4*)(smem + OFF_TAB);
        #pragma unroll
        for (int i = 0; i < 8; ++i) dst[i * 256 + tid] = src[i * 256 + tid];
    }
    // stage A, B tiles (row-major, padded stride)
    {
        const float4* gA = (const float4*)Fn + (size_t)by * 128 * 32;
        const float4* gB = (const float4*)Wn + (size_t)bx * 128 * 32;
        #pragma unroll
        for (int i = 0; i < 16; ++i) {
            int idx = i * 256 + tid;
            int row = idx >> 5, c4 = idx & 31;
            *(float4*)(As + row * LDST + c4 * 4) = gA[idx];
        }
        #pragma unroll
        for (int i = 0; i < 16; ++i) {
            int idx = i * 256 + tid;
            int row = idx >> 5, c4 = idx & 31;
            *(float4*)(Bs + row * LDST + c4 * 4) = gB[idx];
        }
    }
    __syncthreads();

    const int warp_m = wid >> 1, warp_n = wid & 1;
    const int g = lane >> 2, kl = lane & 3;

    float c[2][8][4];
    #pragma unroll
    for (int mt = 0; mt < 2; ++mt)
        #pragma unroll
        for (int nt = 0; nt < 8; ++nt)
            #pragma unroll
            for (int q = 0; q < 4; ++q) c[mt][nt][q] = 0.0f;

    const float* Abase = As + (warp_m * 32 + g) * LDST + kl;
    const float* Bbase = Bs + (warp_n * 64 + g) * LDST + kl;

    #pragma unroll
    for (int ks = 0; ks < 16; ++ks) {
        const int k0 = ks * 8;
        uint32_t a[2][4], b[8][2];
        #pragma unroll
        for (int mt = 0; mt < 2; ++mt) {
            const float* p = Abase + mt * (16 * LDST) + k0;
            a[mt][0] = __float_as_uint(p[0]);
            a[mt][1] = __float_as_uint(p[8 * LDST]);
            a[mt][2] = __float_as_uint(p[4]);
            a[mt][3] = __float_as_uint(p[8 * LDST + 4]);
        }
        #pragma unroll
        for (int nt = 0; nt < 8; ++nt) {
            const float* p = Bbase + nt * (8 * LDST) + k0;
            b[nt][0] = __float_as_uint(p[0]);
            b[nt][1] = __float_as_uint(p[4]);
        }
        #pragma unroll
        for (int mt = 0; mt < 2; ++mt)
            #pragma unroll
            for (int nt = 0; nt < 8; ++nt)
                mma_tf32(c[mt][nt], a[mt], b[nt]);
    }

    // ---- epilogue ----
    float Pu[2][2], tk[2][2];
    #pragma unroll
    for (int mt = 0; mt < 2; ++mt)
        #pragma unroll
        for (int h = 0; h < 2; ++h) {
            int r = by * 128 + warp_m * 32 + mt * 16 + h * 8 + g;
            Pu[mt][h] = g_Pu[r];
            tk[mt][h] = g_2k1[r];
        }

    float rsum[2][2] = {{0.0f, 0.0f}, {0.0f, 0.0f}};
    #pragma unroll
    for (int nt = 0; nt < 8; ++nt) {
        #pragma unroll
        for (int q = 0; q < 2; ++q) {
            int col = warp_n * 64 + nt * 8 + 2 * kl + q;
            float kq = kqS[col], Qh = QhS[col], ez = ezS[col];
            #pragma unroll
            for (int mt = 0; mt < 2; ++mt)
                #pragma unroll
                for (int h = 0; h < 2; ++h) {
                    float dot = c[mt][nt][h * 2 + q];
                    // u = (t3 - tlo2)*invh
                    float u  = fmaf(tk[mt][h], kq * dot, Pu[mt][h] + Qh);
                    float rB = u + MAGIC;
                    int   k  = __float_as_int(rB) - 0x4B400000;   // round(u)
                    float fr = u - (rB - MAGIC);                  // [-0.5, 0.5]
                    float2 te = tab[k];
                    float xf = fmaf(fr, te.y, te.x);              // f(t3)*log2e
                    float y  = xf + ez;                           // bounded ~±30
                    float r2 = y + MAGIC;
                    int   m  = __float_as_int(r2) - 0x4B400000;   // round(y)
                    float f  = y - (r2 - MAGIC);                  // [-0.5, 0.5]
                    float p = 1.33335581e-3f;
                    p = fmaf(p, f, 9.61812910e-3f);
                    p = fmaf(p, f, 5.55041086e-2f);
                    p = fmaf(p, f, 2.40226507e-1f);
                    p = fmaf(p, f, 6.93147181e-1f);
                    p = fmaf(p, f, 1.0f);
                    rsum[mt][h] += __int_as_float(__float_as_int(p) + (m << 23));
                }
        }
    }

    // reduce over kl (4 lanes share a row), store per (row, bx*2+warp_n)
    #pragma unroll
    for (int mt = 0; mt < 2; ++mt)
        #pragma unroll
        for (int h = 0; h < 2; ++h) {
            float s = rsum[mt][h];
            s += __shfl_xor_sync(0xffffffffu, s, 1);
            s += __shfl_xor_sync(0xffffffffu, s, 2);
            if (kl == 0) {
                int r = by * 128 + warp_m * 32 + mt * 16 + h * 8 + g;
                g_partial[(size_t)r * 256 + bx * 2 + warp_n] = s;
            }
        }
}

// ---------------- final reduction ----------------
__global__ void finalize(float* __restrict__ out, int B, int nbx) {
    __shared__ float sred[32];
    int t = threadIdx.x;
    float local = 0.0f;
    for (int r = t; r < B; r += blockDim.x) {
        const float4* p4 = (const float4*)(g_partial + (size_t)r * nbx);
        float S = 0.0f;
        for (int q = 0; q < nbx / 4; ++q) {
            float4 v = p4[q];
            S += (v.x + v.y) + (v.z + v.w);
        }
        local += logf(S) - g_xg[r];
    }
    #pragma unroll
    for (int o = 16; o; o >>= 1) local += __shfl_xor_sync(0xffffffffu, local, o);
    if ((t & 31) == 0) sred[t >> 5] = local;
    __syncthreads();
    if (t < 32) {
        float v = (t < (int)(blockDim.x >> 5)) ? sred[t] : 0.0f;
        #pragma unroll
        for (int o = 16; o; o >>= 1) v += __shfl_xor_sync(0xffffffffu, v, o);
        if (t == 0) out[0] = v / (float)B;
    }
}

// ---------------- launch ----------------
extern "C" void kernel_launch(void* const* d_in, const int* in_sizes, int n_in,
                              void* d_out, int out_size) {
    // inputs: [0]=pred (UNUSED), [1]=unc, [2]=y, [3]=features, [4]=classifier_weight
    const float* unc = (const float*)d_in[1];
    const int*   y   = (const int*)d_in[2];
    const float* F   = (const float*)d_in[3];
    const float* W   = (const float*)d_in[4];
    int B = in_sizes[1];
    int C = in_sizes[4] / DDIM;

    init_minmax<<<1, 1>>>();
    class_norm<<<C / 8, 256>>>(W, C);
    batch_prep<<<B, 128>>>(F, W, unc, y);
    build_table<<<NTAB / 256, 256>>>();
    class_params<<<(C + 255) / 256, 256>>>(C);
    batch_params<<<(B + 255) / 256, 256>>>(B);

    static float* Fn_dev = nullptr;
    static float* Wn_dev = nullptr;
    if (!Fn_dev) {
        cudaGetSymbolAddress((void**)&Fn_dev, g_Fn);
        cudaGetSymbolAddress((void**)&Wn_dev, g_Wn);
        cudaFuncSetAttribute(fused_hmma, cudaFuncAttributeMaxDynamicSharedMemorySize, SMEM_TOTAL);
    }

    dim3 grid(C / 128, B / 128);
    fused_hmma<<<grid, 256, SMEM_TOTAL>>>(Fn_dev, Wn_dev);

    // partials per row = 2 * (C/128)  — R3 bug was passing C/128 here
    finalize<<<1, 1024>>>((float*)d_out, B, 2 * (C / 128));
}

// round 5
// speedup vs baseline: 2.9474x; 1.8214x over previous
#include <cuda_runtime.h>
#include <math.h>
#include <cstdint>

// Problem constants: B=2048, C=16384, D=128
#define BDIM_MAX 2048
#define CDIM_MAX 16384
#define DDIM     128
#define NTAB     1024
#define VF       63.0f
#define V2F      3969.0f
#define L2E      1.4426950408889634f
#define MAGIC    12582912.0f           // 1.5 * 2^23

// -------- device scratch --------
__device__ float  g_Fn[BDIM_MAX * DDIM];
__device__ float  g_Wn[CDIM_MAX * DDIM];
__device__ float  g_kq[CDIM_MAX];            // raw k2, then k2*invh
__device__ float  g_Qh[CDIM_MAX];            // (k2^2 + v^2 - tlo2) * invh
__device__ float  g_ez[CDIM_MAX];            // -e * L2E
__device__ float  g_Pu[BDIM_MAX];            // k1^2 * invh
__device__ float  g_2k1[BDIM_MAX];           // 2*k1
__device__ float  g_xg[BDIM_MAX];            // gathered x at class y_b
__device__ float  g_rowval[BDIM_MAX];
__device__ float  g_partial[BDIM_MAX * 256];
__device__ float2 g_tab[NTAB];
__device__ int    g_k1max_i = 0, g_k2max_i = 0;   // static init; maxes idempotent across replays
__device__ float  g_invh;

// ---------------- helpers ----------------
__device__ __forceinline__ float f_exact(float t) {
    float s = sqrtf(t);
    return s - VF * logf(VF + s) - 0.5f * logf(s);
}

__device__ __forceinline__ float to_tf32(float x) {
    uint32_t r;
    asm("cvt.rna.tf32.f32 %0, %1;" : "=r"(r) : "f"(x));
    return __uint_as_float(r);
}

__device__ __forceinline__ uint32_t smem_u32(const void* p) {
    uint32_t a;
    asm("{ .reg .u64 t; cvta.to.shared.u64 t, %1; cvt.u32.u64 %0, t; }" : "=r"(a) : "l"(p));
    return a;
}

__device__ __forceinline__ void mma_tf32(float* d, const uint32_t* a, const uint32_t* b) {
    asm volatile(
        "mma.sync.aligned.m16n8k8.row.col.f32.tf32.tf32.f32 "
        "{%0,%1,%2,%3}, {%4,%5,%6,%7}, {%8,%9}, {%0,%1,%2,%3};\n"
        : "+f"(d[0]), "+f"(d[1]), "+f"(d[2]), "+f"(d[3])
        : "r"(a[0]), "r"(a[1]), "r"(a[2]), "r"(a[3]), "r"(b[0]), "r"(b[1]));
}

#define LDMX4(r0, r1, r2, r3, addr) \
    asm volatile("ldmatrix.sync.aligned.m8n8.x4.shared.b16 {%0,%1,%2,%3}, [%4];" \
        : "=r"(r0), "=r"(r1), "=r"(r2), "=r"(r3) : "r"(addr))

__device__ __forceinline__ float ex2f(float y) {
    float r;
    asm("ex2.approx.f32 %0, %1;" : "=f"(r) : "f"(y));
    return r;
}

// ---------------- prep kernels ----------------
// one warp per class: normalize row (tf32-rounded), stash raw k2
__global__ void class_norm(const float* __restrict__ W, int C) {
    int c = blockIdx.x * 8 + (threadIdx.x >> 5);
    int lane = threadIdx.x & 31;
    if (c >= C) return;
    float4 w = ((const float4*)W)[c * 32 + lane];
    float ss = w.x*w.x + w.y*w.y + w.z*w.z + w.w*w.w;
    #pragma unroll
    for (int o = 16; o; o >>= 1) ss += __shfl_xor_sync(0xffffffffu, ss, o);
    float nw = sqrtf(ss);
    float inv = 1.0f / nw;
    ((float4*)g_Wn)[c * 32 + lane] = make_float4(
        to_tf32(w.x*inv), to_tf32(w.y*inv), to_tf32(w.z*inv), to_tf32(w.w*inv));
    if (lane == 0) {
        float k2 = fmaxf(nw, 1.0f) * 10.0f;      // INV_TEMP = 10
        g_kq[c] = k2;                             // raw; rescaled in params_table
        atomicMax(&g_k2max_i, __float_as_int(k2));
    }
}

// one block (128 thr) per batch row
__global__ void batch_prep(const float* __restrict__ F, const float* __restrict__ W,
                           const float* __restrict__ unc, const int* __restrict__ y) {
    __shared__ float sred[12];
    __shared__ float s_invnb;
    int b = blockIdx.x;
    int t = threadIdx.x;
    int cls = y[b];
    float fv = F[b * DDIM + t];
    float wv = W[cls * DDIM + t];
    float ssf = fv * fv, ssw = wv * wv, dp = fv * wv;
    #pragma unroll
    for (int o = 16; o; o >>= 1) {
        ssf += __shfl_xor_sync(0xffffffffu, ssf, o);
        ssw += __shfl_xor_sync(0xffffffffu, ssw, o);
        dp  += __shfl_xor_sync(0xffffffffu, dp,  o);
    }
    int w = t >> 5, lane = t & 31;
    if (lane == 0) { sred[w] = ssf; sred[4 + w] = ssw; sred[8 + w] = dp; }
    __syncthreads();
    if (t == 0) {
        float sf = sred[0] + sred[1] + sred[2] + sred[3];
        float sw = sred[4] + sred[5] + sred[6] + sred[7];
        float dt = sred[8] + sred[9] + sred[10] + sred[11];
        float nb = sqrtf(sf), nw = sqrtf(sw);
        float k1 = 1.0f / unc[b];
        g_2k1[b] = 2.0f * k1;
        float k2 = fmaxf(nw, 1.0f) * 10.0f;
        float dotn = dt / (nb * nw);
        float t3 = V2F + k1*k1 + k2*k2 + 2.0f*k1*k2*dotn;
        g_xg[b] = f_exact(t3) - f_exact(V2F + k2 * k2);
        atomicMax(&g_k1max_i, __float_as_int(k1));
        s_invnb = 1.0f / nb;
    }
    __syncthreads();
    g_Fn[b * DDIM + t] = to_tf32(fv * s_invnb);
}

// one kernel: PWL table (analytic slope, fp32) + class params + batch params
__global__ void params_table(int C, int B) {
    int i = blockIdx.x * 256 + threadIdx.x;
    float k1m = __int_as_float(g_k1max_i);
    float k2m = __int_as_float(g_k2max_i);
    float km  = k1m + k2m;
    float range = km * km + 16.0f;
    float h    = range / (float)(NTAB - 2);
    float invh = (float)(NTAB - 2) / range;
    float tlo2 = V2F - h;
    if (i == 0) g_invh = invh;
    if (i < NTAB) {
        float t0 = tlo2 + h * (float)i;
        float s0 = sqrtf(t0);
        float f0 = s0 - VF * logf(VF + s0) - 0.5f * logf(s0);
        float tm = t0 + 0.5f * h;
        float sm = sqrtf(tm);
        float fp = 1.0f / (2.0f * (VF + sm)) - 0.25f / tm;   // f'(t0 + h/2)
        g_tab[i] = make_float2(f0 * L2E, fp * h * L2E);
    }
    if (i < C) {
        float k2 = g_kq[i];
        g_kq[i] = k2 * invh;
        g_Qh[i] = (V2F + k2 * k2 - tlo2) * invh;
        g_ez[i] = -f_exact(V2F + k2 * k2) * L2E;
    }
    if (i < B) {
        float k1 = 0.5f * g_2k1[i];
        g_Pu[i] = k1 * k1 * invh;
    }
}

// ---------------- fused HMMA tf32 GEMM + epilogue ----------------
// CTA: 128 threads (4 warps), tile 64(b) x 128(c), K=128, 2 CTAs/SM.
// Warp tile 32x64: warp_m = wid>>1, warp_n = wid&1.
// smem: params (3*128 f), table (1024 f2), A 64x128 f32, B 128x128 f32,
// both tiles XOR-swizzled on 16B chunks: chunk' = chunk ^ (row & 7).
#define OFF_KQ    0
#define OFF_QH    512
#define OFF_EZ    1024
#define OFF_TAB   2048                    // 8192 bytes
#define OFF_A     10240                   // 32768 bytes (64 rows * 512B)
#define OFF_B     43008                   // 65536 bytes (128 rows * 512B)
#define SMEM_TOTAL (43008 + 65536)        // 108544

__global__ void __launch_bounds__(128, 2)
fused_hmma(const float* __restrict__ Fn, const float* __restrict__ Wn) {
    extern __shared__ char smem[];
    const uint32_t sb = smem_u32(smem);
    float* kqS = (float*)(smem + OFF_KQ);
    float* QhS = (float*)(smem + OFF_QH);
    float* ezS = (float*)(smem + OFF_EZ);
    const float2* tab = (const float2*)(smem + OFF_TAB);

    const int tid = threadIdx.x;
    const int bx = blockIdx.x, by = blockIdx.y;
    const int wid = tid >> 5, lane = tid & 31;

    // stage per-class params
    if (tid < 128) {
        int c = bx * 128 + tid;
        kqS[tid] = g_kq[c];
        QhS[tid] = g_Qh[c];
        ezS[tid] = g_ez[c];
    }
    // stage table (512 float4)
    {
        const float4* src = (const float4*)g_tab;
        float4* dst = (float4*)(smem + OFF_TAB);
        #pragma unroll
        for (int i = 0; i < 4; ++i) dst[i * 128 + tid] = src[i * 128 + tid];
    }
    // stage A (64x128) and B (128x128), XOR-swizzled 16B chunks
    {
        const float4* gA = (const float4*)Fn + (size_t)by * 64 * 32;
        const float4* gB = (const float4*)Wn + (size_t)bx * 128 * 32;
        #pragma unroll
        for (int i = 0; i < 16; ++i) {
            int idx = i * 128 + tid;
            int row = idx >> 5, ch = idx & 31;
            *(float4*)(smem + OFF_A + row * 512 + ((ch ^ (row & 7)) << 4)) = gA[idx];
        }
        #pragma unroll
        for (int i = 0; i < 32; ++i) {
            int idx = i * 128 + tid;
            int row = idx >> 5, ch = idx & 31;
            *(float4*)(smem + OFF_B + row * 512 + ((ch ^ (row & 7)) << 4)) = gB[idx];
        }
    }
    __syncthreads();

    const int warp_m = wid >> 1, warp_n = wid & 1;
    const int g = lane >> 2, kl = lane & 3;
    const int sel = lane >> 3;                 // 0..3: ldmatrix matrix select

    // ldmatrix lane-address bases
    // A, x4 per mt: m0 rows[r0..r0+8) ch c0 | m1 rows+8 ch c0 | m2 rows ch c0+1 | m3 rows+8 ch c0+1
    uint32_t baseA[2], rm7A[2];
    const int csA = sel >> 1;                  // chunk add
    #pragma unroll
    for (int mt = 0; mt < 2; ++mt) {
        int row = warp_m * 32 + mt * 16 + (sel & 1) * 8 + (lane & 7);
        baseA[mt] = sb + OFF_A + row * 512;
        rm7A[mt]  = row & 7;
    }
    // B, x4 per pair p: m0 rows[n0..n0+8) ch c0 | m1 rows ch c0+1 | m2 rows+8 ch c0 | m3 rows+8 ch c0+1
    uint32_t baseB[4], rm7B[4];
    const int csB = sel & 1;
    #pragma unroll
    for (int p = 0; p < 4; ++p) {
        int row = warp_n * 64 + p * 16 + (sel >> 1) * 8 + (lane & 7);
        baseB[p] = sb + OFF_B + row * 512;
        rm7B[p]  = row & 7;
    }

    float acc[2][8][4];
    #pragma unroll
    for (int mt = 0; mt < 2; ++mt)
        #pragma unroll
        for (int nt = 0; nt < 8; ++nt)
            #pragma unroll
            for (int q = 0; q < 4; ++q) acc[mt][nt][q] = 0.0f;

    #pragma unroll
    for (int ks = 0; ks < 16; ++ks) {
        uint32_t a[2][4], b[8][2];
        #pragma unroll
        for (int mt = 0; mt < 2; ++mt) {
            uint32_t ad = baseA[mt] + ((((uint32_t)(2 * ks + csA)) ^ rm7A[mt]) << 4);
            LDMX4(a[mt][0], a[mt][1], a[mt][2], a[mt][3], ad);
        }
        #pragma unroll
        for (int p = 0; p < 4; ++p) {
            uint32_t bd = baseB[p] + ((((uint32_t)(2 * ks + csB)) ^ rm7B[p]) << 4);
            LDMX4(b[2*p][0], b[2*p][1], b[2*p+1][0], b[2*p+1][1], bd);
        }
        #pragma unroll
        for (int mt = 0; mt < 2; ++mt)
            #pragma unroll
            for (int nt = 0; nt < 8; ++nt)
                mma_tf32(acc[mt][nt], a[mt], b[nt]);
    }

    // ---- epilogue ----
    float Pu[2][2], tk[2][2];
    #pragma unroll
    for (int mt = 0; mt < 2; ++mt)
        #pragma unroll
        for (int h = 0; h < 2; ++h) {
            int r = by * 64 + warp_m * 32 + mt * 16 + h * 8 + g;
            Pu[mt][h] = g_Pu[r];
            tk[mt][h] = g_2k1[r];
        }

    float rsum[2][2] = {{0.0f, 0.0f}, {0.0f, 0.0f}};
    #pragma unroll
    for (int nt = 0; nt < 8; ++nt) {
        #pragma unroll
        for (int q = 0; q < 2; ++q) {
            int col = warp_n * 64 + nt * 8 + 2 * kl + q;
            float kq = kqS[col], Qh = QhS[col], ez = ezS[col];
            #pragma unroll
            for (int mt = 0; mt < 2; ++mt)
                #pragma unroll
                for (int h = 0; h < 2; ++h) {
                    float dot = acc[mt][nt][h * 2 + q];
                    float u  = fmaf(tk[mt][h], kq * dot, Pu[mt][h] + Qh);
                    u = fminf(u, (float)(NTAB - 2) + 0.49f);
                    float rB = u + MAGIC;
                    int   k  = __float_as_int(rB) - 0x4B400000;   // round(u)
                    float fr = u - (rB - MAGIC);                  // [-0.5, 0.5]
                    float2 te = tab[k];
                    float xf = fmaf(fr, te.y, te.x);              // f(t3)*log2e
                    rsum[mt][h] += ex2f(xf + ez);
                }
        }
    }

    #pragma unroll
    for (int mt = 0; mt < 2; ++mt)
        #pragma unroll
        for (int h = 0; h < 2; ++h) {
            float s = rsum[mt][h];
            s += __shfl_xor_sync(0xffffffffu, s, 1);
            s += __shfl_xor_sync(0xffffffffu, s, 2);
            if (kl == 0) {
                int r = by * 64 + warp_m * 32 + mt * 16 + h * 8 + g;
                g_partial[(size_t)r * 256 + bx * 2 + warp_n] = s;
            }
        }
}

// ---------------- final reduction (2-stage, parallel) ----------------
__global__ void finalize_rows() {
    int r = blockIdx.x * 8 + (threadIdx.x >> 5);
    int lane = threadIdx.x & 31;
    const float4* p4 = (const float4*)(g_partial + (size_t)r * 256);
    float4 v0 = p4[lane], v1 = p4[lane + 32];
    float S = (v0.x + v0.y) + (v0.z + v0.w) + (v1.x + v1.y) + (v1.z + v1.w);
    #pragma unroll
    for (int o = 16; o; o >>= 1) S += __shfl_xor_sync(0xffffffffu, S, o);
    if (lane == 0) g_rowval[r] = logf(S) - g_xg[r];
}

__global__ void finalize_out(float* __restrict__ out, int B) {
    __shared__ float sred[32];
    int t = threadIdx.x;
    float local = g_rowval[t] + g_rowval[t + 1024];
    #pragma unroll
    for (int o = 16; o; o >>= 1) local += __shfl_xor_sync(0xffffffffu, local, o);
    if ((t & 31) == 0) sred[t >> 5] = local;
    __syncthreads();
    if (t < 32) {
        float v = sred[t];
        #pragma unroll
        for (int o = 16; o; o >>= 1) v += __shfl_xor_sync(0xffffffffu, v, o);
        if (t == 0) out[0] = v / (float)B;
    }
}

// ---------------- launch ----------------
extern "C" void kernel_launch(void* const* d_in, const int* in_sizes, int n_in,
                              void* d_out, int out_size) {
    // inputs: [0]=pred (UNUSED), [1]=unc, [2]=y, [3]=features, [4]=classifier_weight
    const float* unc = (const float*)d_in[1];
    const int*   y   = (const int*)d_in[2];
    const float* F   = (const float*)d_in[3];
    const float* W   = (const float*)d_in[4];
    int B = in_sizes[1];
    int C = in_sizes[4] / DDIM;

    class_norm<<<C / 8, 256>>>(W, C);
    batch_prep<<<B, 128>>>(F, W, unc, y);
    params_table<<<(C + 255) / 256, 256>>>(C, B);

    static float* Fn_dev = nullptr;
    static float* Wn_dev = nullptr;
    if (!Fn_dev) {
        cudaGetSymbolAddress((void**)&Fn_dev, g_Fn);
        cudaGetSymbolAddress((void**)&Wn_dev, g_Wn);
        cudaFuncSetAttribute(fused_hmma, cudaFuncAttributeMaxDynamicSharedMemorySize, SMEM_TOTAL);
    }

    dim3 grid(C / 128, B / 64);                 // (128, 32)
    fused_hmma<<<grid, 128, SMEM_TOTAL>>>(Fn_dev, Wn_dev);

    finalize_rows<<<B / 8, 256>>>();
    finalize_out<<<1, 1024>>>((float*)d_out, B);
}

// round 6
// speedup vs baseline: 3.6508x; 1.2386x over previous
#include <cuda_runtime.h>
#include <math.h>
#include <cstdint>

// Problem constants: B=2048, C=16384, D=128
#define BDIM_MAX 2048
#define CDIM_MAX 16384
#define DDIM     128
#define NTAB     1024
#define VF       63.0f
#define V2F      3969.0f
#define L2E      1.4426950408889634f
#define MAGIC    12582912.0f           // 1.5 * 2^23

// -------- device scratch --------
__device__ float  g_Fn[BDIM_MAX * DDIM];
__device__ float  g_Wn[CDIM_MAX * DDIM];
__device__ float  g_kq[CDIM_MAX];            // raw k2, then k2*invh
__device__ float  g_Qh[CDIM_MAX];            // (k2^2 + v^2 - tlo2) * invh
__device__ float  g_ez[CDIM_MAX];            // -e * L2E
__device__ float  g_Pu[BDIM_MAX];            // k1^2 * invh
__device__ float  g_2k1[BDIM_MAX];           // 2*k1
__device__ float  g_xg[BDIM_MAX];            // gathered x at class y_b
__device__ float  g_rowval[BDIM_MAX];
__device__ float  g_partial[BDIM_MAX * 256];
__device__ float2 g_tab[NTAB];
__device__ int    g_k1max_i = 0, g_k2max_i = 0;   // maxes idempotent across replays
__device__ float  g_invh;

// ---------------- helpers ----------------
__device__ __forceinline__ float f_exact(float t) {
    float s = sqrtf(t);
    return s - VF * logf(VF + s) - 0.5f * logf(s);
}

__device__ __forceinline__ float to_tf32(float x) {
    uint32_t r;
    asm("cvt.rna.tf32.f32 %0, %1;" : "=r"(r) : "f"(x));
    return __uint_as_float(r);
}

__device__ __forceinline__ uint32_t smem_u32(const void* p) {
    uint32_t a;
    asm("{ .reg .u64 t; cvta.to.shared.u64 t, %1; cvt.u32.u64 %0, t; }" : "=r"(a) : "l"(p));
    return a;
}

__device__ __forceinline__ void mma_tf32(float* d, const uint32_t* a, const uint32_t* b) {
    asm volatile(
        "mma.sync.aligned.m16n8k8.row.col.f32.tf32.tf32.f32 "
        "{%0,%1,%2,%3}, {%4,%5,%6,%7}, {%8,%9}, {%0,%1,%2,%3};\n"
        : "+f"(d[0]), "+f"(d[1]), "+f"(d[2]), "+f"(d[3])
        : "r"(a[0]), "r"(a[1]), "r"(a[2]), "r"(a[3]), "r"(b[0]), "r"(b[1]));
}

#define LDMX4(r0, r1, r2, r3, addr) \
    asm volatile("ldmatrix.sync.aligned.m8n8.x4.shared.b16 {%0,%1,%2,%3}, [%4];" \
        : "=r"(r0), "=r"(r1), "=r"(r2), "=r"(r3) : "r"(addr))

#define CPA16(dst, src) \
    asm volatile("cp.async.cg.shared.global [%0], [%1], 16;" :: "r"(dst), "l"(src))

__device__ __forceinline__ float ex2f(float y) {
    float r;
    asm("ex2.approx.f32 %0, %1;" : "=f"(r) : "f"(y));
    return r;
}

// ---------------- prep kernels ----------------
__global__ void class_norm(const float* __restrict__ W, int C) {
    int c = blockIdx.x * 8 + (threadIdx.x >> 5);
    int lane = threadIdx.x & 31;
    if (c >= C) return;
    float4 w = ((const float4*)W)[c * 32 + lane];
    float ss = w.x*w.x + w.y*w.y + w.z*w.z + w.w*w.w;
    #pragma unroll
    for (int o = 16; o; o >>= 1) ss += __shfl_xor_sync(0xffffffffu, ss, o);
    float nw = sqrtf(ss);
    float inv = 1.0f / nw;
    ((float4*)g_Wn)[c * 32 + lane] = make_float4(
        to_tf32(w.x*inv), to_tf32(w.y*inv), to_tf32(w.z*inv), to_tf32(w.w*inv));
    if (lane == 0) {
        float k2 = fmaxf(nw, 1.0f) * 10.0f;      // INV_TEMP = 10
        g_kq[c] = k2;
        atomicMax(&g_k2max_i, __float_as_int(k2));
    }
}

__global__ void batch_prep(const float* __restrict__ F, const float* __restrict__ W,
                           const float* __restrict__ unc, const int* __restrict__ y) {
    __shared__ float sred[12];
    __shared__ float s_invnb;
    int b = blockIdx.x;
    int t = threadIdx.x;
    int cls = y[b];
    float fv = F[b * DDIM + t];
    float wv = W[cls * DDIM + t];
    float ssf = fv * fv, ssw = wv * wv, dp = fv * wv;
    #pragma unroll
    for (int o = 16; o; o >>= 1) {
        ssf += __shfl_xor_sync(0xffffffffu, ssf, o);
        ssw += __shfl_xor_sync(0xffffffffu, ssw, o);
        dp  += __shfl_xor_sync(0xffffffffu, dp,  o);
    }
    int w = t >> 5, lane = t & 31;
    if (lane == 0) { sred[w] = ssf; sred[4 + w] = ssw; sred[8 + w] = dp; }
    __syncthreads();
    if (t == 0) {
        float sf = sred[0] + sred[1] + sred[2] + sred[3];
        float sw = sred[4] + sred[5] + sred[6] + sred[7];
        float dt = sred[8] + sred[9] + sred[10] + sred[11];
        float nb = sqrtf(sf), nw = sqrtf(sw);
        float k1 = 1.0f / unc[b];
        g_2k1[b] = 2.0f * k1;
        float k2 = fmaxf(nw, 1.0f) * 10.0f;
        float dotn = dt / (nb * nw);
        float t3 = V2F + k1*k1 + k2*k2 + 2.0f*k1*k2*dotn;
        g_xg[b] = f_exact(t3) - f_exact(V2F + k2 * k2);
        atomicMax(&g_k1max_i, __float_as_int(k1));
        s_invnb = 1.0f / nb;
    }
    __syncthreads();
    g_Fn[b * DDIM + t] = to_tf32(fv * s_invnb);
}

__global__ void params_table(int C, int B) {
    int i = blockIdx.x * 256 + threadIdx.x;
    float k1m = __int_as_float(g_k1max_i);
    float k2m = __int_as_float(g_k2max_i);
    float km  = k1m + k2m;
    float range = km * km + 16.0f;
    float h    = range / (float)(NTAB - 2);
    float invh = (float)(NTAB - 2) / range;
    float tlo2 = V2F - h;
    if (i == 0) g_invh = invh;
    if (i < NTAB) {
        float t0 = tlo2 + h * (float)i;
        float s0 = sqrtf(t0);
        float f0 = s0 - VF * logf(VF + s0) - 0.5f * logf(s0);
        float tm = t0 + 0.5f * h;
        float sm = sqrtf(tm);
        float fp = 1.0f / (2.0f * (VF + sm)) - 0.25f / tm;   // f'(t0 + h/2)
        g_tab[i] = make_float2(f0 * L2E, fp * h * L2E);
    }
    if (i < C) {
        float k2 = g_kq[i];
        g_kq[i] = k2 * invh;
        g_Qh[i] = (V2F + k2 * k2 - tlo2) * invh;
        g_ez[i] = -f_exact(V2F + k2 * k2) * L2E;
    }
    if (i < B) {
        float k1 = 0.5f * g_2k1[i];
        g_Pu[i] = k1 * k1 * invh;
    }
}

// ---------------- fused HMMA tf32 GEMM + epilogue ----------------
// CTA: 128 threads (4 warps), tile 128(b) x 128(c), 2 CTAs/SM.
// Warp tile 64x64: warp_m = wid>>1, warp_n = wid&1.
// K pipelined in 4 chunks of 32 via cp.async double buffering.
// Chunk layout: [128 rows][8 x 16B chunks], chunk' = ch ^ (row & 7).
#define OFF_KQ    0
#define OFF_QH    512
#define OFF_EZ    1024
#define OFF_TAB   2048                    // 8192 bytes
#define OFF_A     10240                   // 2 x 16384
#define OFF_B     43008                   // 2 x 16384
#define SMEM_TOTAL (43008 + 32768)        // 75776

__global__ void __launch_bounds__(128, 2)
fused_hmma(const float* __restrict__ Fn, const float* __restrict__ Wn) {
    extern __shared__ char smem[];
    const uint32_t sb = smem_u32(smem);
    float* kqS = (float*)(smem + OFF_KQ);
    float* QhS = (float*)(smem + OFF_QH);
    float* ezS = (float*)(smem + OFF_EZ);
    const float2* tab = (const float2*)(smem + OFF_TAB);

    const int tid = threadIdx.x;
    const int bx = blockIdx.x, by = blockIdx.y;
    const int wid = tid >> 5, lane = tid & 31;

    // stage per-class params + table
    {
        int c = bx * 128 + tid;
        kqS[tid] = g_kq[c];
        QhS[tid] = g_Qh[c];
        ezS[tid] = g_ez[c];
        const float4* src = (const float4*)g_tab;
        float4* dst = (float4*)(smem + OFF_TAB);
        #pragma unroll
        for (int i = 0; i < 4; ++i) dst[i * 128 + tid] = src[i * 128 + tid];
    }

    const float* gA = Fn + (size_t)by * 128 * 128;
    const float* gB = Wn + (size_t)bx * 128 * 128;
    const int prow = tid >> 3;          // preload row group base (16 rows/iter)
    const int pch  = tid & 7;

    // prefetch chunk c into buffer c&1
    #define PREFETCH(c) do {                                                        \
        uint32_t bufA = sb + OFF_A + ((c) & 1) * 16384;                             \
        uint32_t bufB = sb + OFF_B + ((c) & 1) * 16384;                             \
        _Pragma("unroll")                                                           \
        for (int i = 0; i < 8; ++i) {                                               \
            int row = i * 16 + prow;                                                \
            uint32_t so = row * 128 + (((uint32_t)(pch ^ (row & 7))) << 4);         \
            const float* ga = gA + row * 128 + (c) * 32 + pch * 4;                  \
            const float* gb = gB + row * 128 + (c) * 32 + pch * 4;                  \
            CPA16(bufA + so, ga);                                                   \
            CPA16(bufB + so, gb);                                                   \
        }                                                                           \
        asm volatile("cp.async.commit_group;" ::: "memory");                        \
    } while (0)

    PREFETCH(0);

    const int warp_m = wid >> 1, warp_n = wid & 1;
    const int g = lane >> 2, kl = lane & 3;
    const int sel = lane >> 3;

    // ldmatrix lane-address bases (within a chunk buffer)
    uint32_t offA[4], rm7A[4];
    const uint32_t csA = sel >> 1;
    #pragma unroll
    for (int mt = 0; mt < 4; ++mt) {
        int row = warp_m * 64 + mt * 16 + (sel & 1) * 8 + (lane & 7);
        offA[mt] = row * 128;
        rm7A[mt] = row & 7;
    }
    uint32_t offB[4], rm7B[4];
    const uint32_t csB = sel & 1;
    #pragma unroll
    for (int p = 0; p < 4; ++p) {
        int row = warp_n * 64 + p * 16 + (sel >> 1) * 8 + (lane & 7);
        offB[p] = row * 128;
        rm7B[p] = row & 7;
    }

    float acc[4][8][4];
    #pragma unroll
    for (int mt = 0; mt < 4; ++mt)
        #pragma unroll
        for (int nt = 0; nt < 8; ++nt)
            #pragma unroll
            for (int q = 0; q < 4; ++q) acc[mt][nt][q] = 0.0f;

    #pragma unroll
    for (int c = 0; c < 4; ++c) {
        if (c < 3) {
            PREFETCH(c + 1);
            asm volatile("cp.async.wait_group 1;" ::: "memory");
        } else {
            asm volatile("cp.async.wait_group 0;" ::: "memory");
        }
        __syncthreads();

        uint32_t bufA = sb + OFF_A + (c & 1) * 16384;
        uint32_t bufB = sb + OFF_B + (c & 1) * 16384;
        #pragma unroll
        for (int kc = 0; kc < 4; ++kc) {
            uint32_t a[4][4], b[8][2];
            #pragma unroll
            for (int mt = 0; mt < 4; ++mt) {
                uint32_t ad = bufA + offA[mt]
                            + ((((uint32_t)(2 * kc) + csA) ^ rm7A[mt]) << 4);
                LDMX4(a[mt][0], a[mt][1], a[mt][2], a[mt][3], ad);
            }
            #pragma unroll
            for (int p = 0; p < 4; ++p) {
                uint32_t bd = bufB + offB[p]
                            + ((((uint32_t)(2 * kc) + csB) ^ rm7B[p]) << 4);
                LDMX4(b[2*p][0], b[2*p][1], b[2*p+1][0], b[2*p+1][1], bd);
            }
            #pragma unroll
            for (int mt = 0; mt < 4; ++mt)
                #pragma unroll
                for (int nt = 0; nt < 8; ++nt)
                    mma_tf32(acc[mt][nt], a[mt], b[nt]);
        }
        __syncthreads();   // all warps done with buffer (c&1) before overwrite
    }

    // ---- epilogue ----
    float Pu[4][2], tk[4][2];
    #pragma unroll
    for (int mt = 0; mt < 4; ++mt)
        #pragma unroll
        for (int h = 0; h < 2; ++h) {
            int r = by * 128 + warp_m * 64 + mt * 16 + h * 8 + g;
            Pu[mt][h] = g_Pu[r];
            tk[mt][h] = g_2k1[r];
        }

    float rsum[4][2];
    #pragma unroll
    for (int mt = 0; mt < 4; ++mt) { rsum[mt][0] = 0.0f; rsum[mt][1] = 0.0f; }

    #pragma unroll
    for (int nt = 0; nt < 8; ++nt) {
        #pragma unroll
        for (int q = 0; q < 2; ++q) {
            int col = warp_n * 64 + nt * 8 + 2 * kl + q;
            float kq = kqS[col], Qh = QhS[col], ez = ezS[col];
            #pragma unroll
            for (int mt = 0; mt < 4; ++mt)
                #pragma unroll
                for (int h = 0; h < 2; ++h) {
                    float dot = acc[mt][nt][h * 2 + q];
                    float u  = fmaf(tk[mt][h], kq * dot, Pu[mt][h] + Qh);
                    u = fminf(u, (float)(NTAB - 2) + 0.49f);
                    float rB = u + MAGIC;
                    int   k  = __float_as_int(rB) - 0x4B400000;   // round(u)
                    float fr = u - (rB - MAGIC);                  // [-0.5, 0.5]
                    float2 te = tab[k];
                    float xf = fmaf(fr, te.y, te.x);              // f(t3)*log2e
                    rsum[mt][h] += ex2f(xf + ez);
                }
        }
    }

    #pragma unroll
    for (int mt = 0; mt < 4; ++mt)
        #pragma unroll
        for (int h = 0; h < 2; ++h) {
            float s = rsum[mt][h];
            s += __shfl_xor_sync(0xffffffffu, s, 1);
            s += __shfl_xor_sync(0xffffffffu, s, 2);
            if (kl == 0) {
                int r = by * 128 + warp_m * 64 + mt * 16 + h * 8 + g;
                g_partial[(size_t)r * 256 + bx * 2 + warp_n] = s;
            }
        }
}

// ---------------- final reduction (2-stage, parallel) ----------------
__global__ void finalize_rows() {
    int r = blockIdx.x * 8 + (threadIdx.x >> 5);
    int lane = threadIdx.x & 31;
    const float4* p4 = (const float4*)(g_partial + (size_t)r * 256);
    float4 v0 = p4[lane], v1 = p4[lane + 32];
    float S = (v0.x + v0.y) + (v0.z + v0.w) + (v1.x + v1.y) + (v1.z + v1.w);
    #pragma unroll
    for (int o = 16; o; o >>= 1) S += __shfl_xor_sync(0xffffffffu, S, o);
    if (lane == 0) g_rowval[r] = logf(S) - g_xg[r];
}

__global__ void finalize_out(float* __restrict__ out, int B) {
    __shared__ float sred[32];
    int t = threadIdx.x;
    float local = g_rowval[t] + g_rowval[t + 1024];
    #pragma unroll
    for (int o = 16; o; o >>= 1) local += __shfl_xor_sync(0xffffffffu, local, o);
    if ((t & 31) == 0) sred[t >> 5] = local;
    __syncthreads();
    if (t < 32) {
        float v = sred[t];
        #pragma unroll
        for (int o = 16; o; o >>= 1) v += __shfl_xor_sync(0xffffffffu, v, o);
        if (t == 0) out[0] = v / (float)B;
    }
}

// ---------------- launch ----------------
extern "C" void kernel_launch(void* const* d_in, const int* in_sizes, int n_in,
                              void* d_out, int out_size) {
    // inputs: [0]=pred (UNUSED), [1]=unc, [2]=y, [3]=features, [4]=classifier_weight
    const float* unc = (const float*)d_in[1];
    const int*   y   = (const int*)d_in[2];
    const float* F   = (const float*)d_in[3];
    const float* W   = (const float*)d_in[4];
    int B = in_sizes[1];
    int C = in_sizes[4] / DDIM;

    class_norm<<<C / 8, 256>>>(W, C);
    batch_prep<<<B, 128>>>(F, W, unc, y);
    params_table<<<(C + 255) / 256, 256>>>(C, B);

    static float* Fn_dev = nullptr;
    static float* Wn_dev = nullptr;
    if (!Fn_dev) {
        cudaGetSymbolAddress((void**)&Fn_dev, g_Fn);
        cudaGetSymbolAddress((void**)&Wn_dev, g_Wn);
        cudaFuncSetAttribute(fused_hmma, cudaFuncAttributeMaxDynamicSharedMemorySize, SMEM_TOTAL);
    }

    dim3 grid(C / 128, B / 128);                 // (128, 16)
    fused_hmma<<<grid, 128, SMEM_TOTAL>>>(Fn_dev, Wn_dev);

    finalize_rows<<<B / 8, 256>>>();
    finalize_out<<<1, 1024>>>((float*)d_out, B);
}

// round 7
// speedup vs baseline: 4.0445x; 1.1078x over previous
#include <cuda_runtime.h>
#include <math.h>
#include <cstdint>

// Problem constants: B=2048, C=16384, D=128
#define BDIM_MAX 2048
#define CDIM_MAX 16384
#define DDIM     128
#define NTAB     1024
#define VF       63.0f
#define V2F      3969.0f
#define L2E      1.4426950408889634f
#define MAGIC    12582912.0f           // 1.5 * 2^23

// -------- device scratch --------
__device__ float  g_Fn[BDIM_MAX * DDIM];     // normalized features (tf32)
__device__ float  g_Wn[CDIM_MAX * DDIM];     // normalized rows * k2 (tf32)
__device__ float  g_kq[CDIM_MAX];            // raw k2
__device__ float2 g_parC[CDIM_MAX];          // (Qh, ez)
__device__ float  g_Pu[BDIM_MAX];            // k1^2 * invh
__device__ float  g_a[BDIM_MAX];             // 2*k1 * invh
__device__ float  g_k1[BDIM_MAX];            // k1
__device__ float  g_xg[BDIM_MAX];            // gathered x at class y_b
__device__ float  g_rowval[BDIM_MAX];
__device__ float  g_partial[BDIM_MAX * 256];
__device__ float2 g_tab[NTAB];
__device__ int    g_k1max_i = 0, g_k2max_i = 0;   // maxes idempotent across replays
__device__ float  g_invh;

// ---------------- helpers ----------------
__device__ __forceinline__ float f_exact(float t) {
    float s = sqrtf(t);
    return s - VF * logf(VF + s) - 0.5f * logf(s);
}

__device__ __forceinline__ float to_tf32(float x) {
    uint32_t r;
    asm("cvt.rna.tf32.f32 %0, %1;" : "=r"(r) : "f"(x));
    return __uint_as_float(r);
}

__device__ __forceinline__ uint32_t smem_u32(const void* p) {
    uint32_t a;
    asm("{ .reg .u64 t; cvta.to.shared.u64 t, %1; cvt.u32.u64 %0, t; }" : "=r"(a) : "l"(p));
    return a;
}

__device__ __forceinline__ void mma_tf32(float* d, const uint32_t* a, const uint32_t* b) {
    asm volatile(
        "mma.sync.aligned.m16n8k8.row.col.f32.tf32.tf32.f32 "
        "{%0,%1,%2,%3}, {%4,%5,%6,%7}, {%8,%9}, {%0,%1,%2,%3};\n"
        : "+f"(d[0]), "+f"(d[1]), "+f"(d[2]), "+f"(d[3])
        : "r"(a[0]), "r"(a[1]), "r"(a[2]), "r"(a[3]), "r"(b[0]), "r"(b[1]));
}

#define LDMX4(r0, r1, r2, r3, addr) \
    asm volatile("ldmatrix.sync.aligned.m8n8.x4.shared.b16 {%0,%1,%2,%3}, [%4];" \
        : "=r"(r0), "=r"(r1), "=r"(r2), "=r"(r3) : "r"(addr))

#define CPA16(dst, src) \
    asm volatile("cp.async.cg.shared.global [%0], [%1], 16;" :: "r"(dst), "l"(src))

__device__ __forceinline__ float ex2f(float y) {
    float r;
    asm("ex2.approx.f32 %0, %1;" : "=f"(r) : "f"(y));
    return r;
}

// ---------------- prep: classes (warp each) + batch rows (half-block each) --
__global__ void prep(const float* __restrict__ W, const float* __restrict__ F,
                     const float* __restrict__ unc, const int* __restrict__ y,
                     int nClassBlocks) {
    if ((int)blockIdx.x < nClassBlocks) {
        // ---- class part: 8 classes per 256-thr block, one warp each ----
        int c = blockIdx.x * 8 + (threadIdx.x >> 5);
        int lane = threadIdx.x & 31;
        float4 w = ((const float4*)W)[c * 32 + lane];
        float ss = w.x*w.x + w.y*w.y + w.z*w.z + w.w*w.w;
        #pragma unroll
        for (int o = 16; o; o >>= 1) ss += __shfl_xor_sync(0xffffffffu, ss, o);
        float nw = sqrtf(ss);
        float k2 = fmaxf(nw, 1.0f) * 10.0f;       // INV_TEMP = 10
        float sc = k2 / nw;                       // fold k2 into operand
        ((float4*)g_Wn)[c * 32 + lane] = make_float4(
            to_tf32(w.x*sc), to_tf32(w.y*sc), to_tf32(w.z*sc), to_tf32(w.w*sc));
        if (lane == 0) {
            g_kq[c] = k2;
            atomicMax(&g_k2max_i, __float_as_int(k2));
        }
    } else {
        // ---- batch part: 2 rows per 256-thr block ----
        __shared__ float sred[2][12];
        __shared__ float s_invnb[2];
        int half = threadIdx.x >> 7;          // 0 or 1
        int t    = threadIdx.x & 127;
        int b    = (blockIdx.x - nClassBlocks) * 2 + half;
        int cls = y[b];
        float fv = F[b * DDIM + t];
        float wv = W[cls * DDIM + t];
        float ssf = fv * fv, ssw = wv * wv, dp = fv * wv;
        #pragma unroll
        for (int o = 16; o; o >>= 1) {
            ssf += __shfl_xor_sync(0xffffffffu, ssf, o);
            ssw += __shfl_xor_sync(0xffffffffu, ssw, o);
            dp  += __shfl_xor_sync(0xffffffffu, dp,  o);
        }
        int w = t >> 5, lane = t & 31;
        if (lane == 0) { sred[half][w] = ssf; sred[half][4 + w] = ssw; sred[half][8 + w] = dp; }
        __syncthreads();
        if (t == 0) {
            float sf = sred[half][0] + sred[half][1] + sred[half][2] + sred[half][3];
            float sw = sred[half][4] + sred[half][5] + sred[half][6] + sred[half][7];
            float dt = sred[half][8] + sred[half][9] + sred[half][10] + sred[half][11];
            float nb = sqrtf(sf), nw = sqrtf(sw);
            float k1 = 1.0f / unc[b];
            g_k1[b] = k1;
            float k2 = fmaxf(nw, 1.0f) * 10.0f;
            float dotn = dt / (nb * nw);
            float t3 = V2F + k1*k1 + k2*k2 + 2.0f*k1*k2*dotn;
            g_xg[b] = f_exact(t3) - f_exact(V2F + k2 * k2);
            atomicMax(&g_k1max_i, __float_as_int(k1));
            s_invnb[half] = 1.0f / nb;
        }
        __syncthreads();
        g_Fn[b * DDIM + t] = to_tf32(fv * s_invnb[half]);
    }
}

// PWL table (analytic slope) + per-class float2 + per-row params
__global__ void params_table(int C, int B) {
    int i = blockIdx.x * 256 + threadIdx.x;
    float k1m = __int_as_float(g_k1max_i);
    float k2m = __int_as_float(g_k2max_i);
    float km  = k1m + k2m;
    float range = km * km + 16.0f;
    float h    = range / (float)(NTAB - 2);
    float invh = (float)(NTAB - 2) / range;
    float tlo2 = V2F - h;
    if (i == 0) g_invh = invh;
    if (i < NTAB) {
        float t0 = tlo2 + h * (float)i;
        float s0 = sqrtf(t0);
        float f0 = s0 - VF * logf(VF + s0) - 0.5f * logf(s0);
        float tm = t0 + 0.5f * h;
        float sm = sqrtf(tm);
        float fp = 1.0f / (2.0f * (VF + sm)) - 0.25f / tm;   // f'(t0 + h/2)
        g_tab[i] = make_float2(f0 * L2E, fp * h * L2E);
    }
    if (i < C) {
        float k2 = g_kq[i];
        g_parC[i] = make_float2((V2F + k2 * k2 - tlo2) * invh,
                                -f_exact(V2F + k2 * k2) * L2E);
    }
    if (i < B) {
        float k1 = g_k1[i];
        g_Pu[i] = k1 * k1 * invh;
        g_a[i]  = 2.0f * k1 * invh;
    }
}

// ---------------- fused HMMA tf32 GEMM + epilogue ----------------
// CTA: 128 threads (4 warps), tile 128(b) x 128(c), 2 CTAs/SM.
// Warp tile 64x64. K in 4 chunks of 32, 3-stage cp.async ring (1 sync/chunk).
// Chunk layout: [128 rows][8 x 16B chunks], chunk' = ch ^ (row & 7).
#define OFF_PAR   0                        // 128 * float2 = 1024
#define OFF_TAB   1024                     // 8192
#define OFF_A     9216                     // 3 x 16384
#define OFF_B     58368                    // 3 x 16384
#define SMEM_TOTAL (58368 + 49152)         // 107520

__global__ void __launch_bounds__(128, 2)
fused_hmma(const float* __restrict__ Fn, const float* __restrict__ Wn) {
    extern __shared__ char smem[];
    const uint32_t sb = smem_u32(smem);
    float2* parS = (float2*)(smem + OFF_PAR);
    const float2* tab = (const float2*)(smem + OFF_TAB);

    const int tid = threadIdx.x;
    const int bx = blockIdx.x, by = blockIdx.y;
    const int wid = tid >> 5, lane = tid & 31;

    const float* gA = Fn + (size_t)by * 128 * 128;
    const float* gB = Wn + (size_t)bx * 128 * 128;
    const int prow = tid >> 3;
    const int pch  = tid & 7;

    // prefetch chunk c into stage s
    #define PREFETCH(c, s) do {                                                     \
        uint32_t bufA = sb + OFF_A + (s) * 16384;                                   \
        uint32_t bufB = sb + OFF_B + (s) * 16384;                                   \
        _Pragma("unroll")                                                           \
        for (int i = 0; i < 8; ++i) {                                               \
            int row = i * 16 + prow;                                                \
            uint32_t so = row * 128 + (((uint32_t)(pch ^ (row & 7))) << 4);         \
            CPA16(bufA + so, gA + row * 128 + (c) * 32 + pch * 4);                  \
            CPA16(bufB + so, gB + row * 128 + (c) * 32 + pch * 4);                  \
        }                                                                           \
        asm volatile("cp.async.commit_group;" ::: "memory");                        \
    } while (0)

    PREFETCH(0, 0);
    PREFETCH(1, 1);

    // stage per-class params + table while prefetch is in flight
    {
        parS[tid] = g_parC[bx * 128 + tid];
        const float4* src = (const float4*)g_tab;
        float4* dst = (float4*)(smem + OFF_TAB);
        #pragma unroll
        for (int i = 0; i < 4; ++i) dst[i * 128 + tid] = src[i * 128 + tid];
    }

    const int warp_m = wid >> 1, warp_n = wid & 1;
    const int g = lane >> 2, kl = lane & 3;
    const int sel = lane >> 3;

    uint32_t offA[4], rm7A[4];
    const uint32_t csA = sel >> 1;
    #pragma unroll
    for (int mt = 0; mt < 4; ++mt) {
        int row = warp_m * 64 + mt * 16 + (sel & 1) * 8 + (lane & 7);
        offA[mt] = row * 128;
        rm7A[mt] = row & 7;
    }
    uint32_t offB[4], rm7B[4];
    const uint32_t csB = sel & 1;
    #pragma unroll
    for (int p = 0; p < 4; ++p) {
        int row = warp_n * 64 + p * 16 + (sel >> 1) * 8 + (lane & 7);
        offB[p] = row * 128;
        rm7B[p] = row & 7;
    }

    float acc[4][8][4];
    #pragma unroll
    for (int mt = 0; mt < 4; ++mt)
        #pragma unroll
        for (int nt = 0; nt < 8; ++nt)
            #pragma unroll
            for (int q = 0; q < 4; ++q) acc[mt][nt][q] = 0.0f;

    #pragma unroll
    for (int c = 0; c < 4; ++c) {
        if (c < 3) asm volatile("cp.async.wait_group 1;" ::: "memory");
        else       asm volatile("cp.async.wait_group 0;" ::: "memory");
        __syncthreads();

        uint32_t bufA = sb + OFF_A + (c % 3) * 16384;
        uint32_t bufB = sb + OFF_B + (c % 3) * 16384;
        #pragma unroll
        for (int kc = 0; kc < 4; ++kc) {
            uint32_t a[4][4], b[8][2];
            #pragma unroll
            for (int mt = 0; mt < 4; ++mt) {
                uint32_t ad = bufA + offA[mt]
                            + ((((uint32_t)(2 * kc) + csA) ^ rm7A[mt]) << 4);
                LDMX4(a[mt][0], a[mt][1], a[mt][2], a[mt][3], ad);
            }
            #pragma unroll
            for (int p = 0; p < 4; ++p) {
                uint32_t bd = bufB + offB[p]
                            + ((((uint32_t)(2 * kc) + csB) ^ rm7B[p]) << 4);
                LDMX4(b[2*p][0], b[2*p][1], b[2*p+1][0], b[2*p+1][1], bd);
            }
            #pragma unroll
            for (int mt = 0; mt < 4; ++mt)
                #pragma unroll
                for (int nt = 0; nt < 8; ++nt)
                    mma_tf32(acc[mt][nt], a[mt], b[nt]);
        }
        if (c < 2) PREFETCH(c + 2, (c + 2) % 3);
    }

    // ---- epilogue ----
    float Pu[4][2], ar[4][2];
    #pragma unroll
    for (int mt = 0; mt < 4; ++mt)
        #pragma unroll
        for (int h = 0; h < 2; ++h) {
            int r = by * 128 + warp_m * 64 + mt * 16 + h * 8 + g;
            Pu[mt][h] = g_Pu[r];
            ar[mt][h] = g_a[r];
        }

    float rsum[4][2];
    #pragma unroll
    for (int mt = 0; mt < 4; ++mt) { rsum[mt][0] = 0.0f; rsum[mt][1] = 0.0f; }

    #pragma unroll
    for (int nt = 0; nt < 8; ++nt) {
        #pragma unroll
        for (int q = 0; q < 2; ++q) {
            int col = warp_n * 64 + nt * 8 + 2 * kl + q;
            float2 pe = parS[col];                 // (Qh, ez)
            #pragma unroll
            for (int mt = 0; mt < 4; ++mt)
                #pragma unroll
                for (int h = 0; h < 2; ++h) {
                    float dot2 = acc[mt][nt][h * 2 + q];      // k2 * cos
                    float u  = fmaf(ar[mt][h], dot2, Pu[mt][h] + pe.x);
                    float rB = u + MAGIC;
                    int   k  = __float_as_int(rB) - 0x4B400000;  // round(u)
                    float fr = u - (rB - MAGIC);                 // [-0.5, 0.5]
                    float2 te = tab[k];
                    float y  = fmaf(fr, te.y, te.x) + pe.y;      // log2 exp arg
                    rsum[mt][h] += ex2f(y);
                }
        }
    }

    #pragma unroll
    for (int mt = 0; mt < 4; ++mt)
        #pragma unroll
        for (int h = 0; h < 2; ++h) {
            float s = rsum[mt][h];
            s += __shfl_xor_sync(0xffffffffu, s, 1);
            s += __shfl_xor_sync(0xffffffffu, s, 2);
            if (kl == 0) {
                int r = by * 128 + warp_m * 64 + mt * 16 + h * 8 + g;
                g_partial[(size_t)r * 256 + bx * 2 + warp_n] = s;
            }
        }
}

// ---------------- final reduction (2-stage, parallel) ----------------
__global__ void finalize_rows() {
    int r = blockIdx.x * 8 + (threadIdx.x >> 5);
    int lane = threadIdx.x & 31;
    const float4* p4 = (const float4*)(g_partial + (size_t)r * 256);
    float4 v0 = p4[lane], v1 = p4[lane + 32];
    float S = (v0.x + v0.y) + (v0.z + v0.w) + (v1.x + v1.y) + (v1.z + v1.w);
    #pragma unroll
    for (int o = 16; o; o >>= 1) S += __shfl_xor_sync(0xffffffffu, S, o);
    if (lane == 0) g_rowval[r] = logf(S) - g_xg[r];
}

__global__ void finalize_out(float* __restrict__ out, int B) {
    __shared__ float sred[32];
    int t = threadIdx.x;
    float local = g_rowval[t] + g_rowval[t + 1024];
    #pragma unroll
    for (int o = 16; o; o >>= 1) local += __shfl_xor_sync(0xffffffffu, local, o);
    if ((t & 31) == 0) sred[t >> 5] = local;
    __syncthreads();
    if (t < 32) {
        float v = sred[t];
        #pragma unroll
        for (int o = 16; o; o >>= 1) v += __shfl_xor_sync(0xffffffffu, v, o);
        if (t == 0) out[0] = v / (float)B;
    }
}

// ---------------- launch ----------------
extern "C" void kernel_launch(void* const* d_in, const int* in_sizes, int n_in,
                              void* d_out, int out_size) {
    // inputs: [0]=pred (UNUSED), [1]=unc, [2]=y, [3]=features, [4]=classifier_weight
    const float* unc = (const float*)d_in[1];
    const int*   y   = (const int*)d_in[2];
    const float* F   = (const float*)d_in[3];
    const float* W   = (const float*)d_in[4];
    int B = in_sizes[1];
    int C = in_sizes[4] / DDIM;

    int nClassBlocks = C / 8;
    prep<<<nClassBlocks + B / 2, 256>>>(W, F, unc, y, nClassBlocks);
    params_table<<<(C + 255) / 256, 256>>>(C, B);

    static float* Fn_dev = nullptr;
    static float* Wn_dev = nullptr;
    if (!Fn_dev) {
        cudaGetSymbolAddress((void**)&Fn_dev, g_Fn);
        cudaGetSymbolAddress((void**)&Wn_dev, g_Wn);
        cudaFuncSetAttribute(fused_hmma, cudaFuncAttributeMaxDynamicSharedMemorySize, SMEM_TOTAL);
    }

    dim3 grid(C / 128, B / 128);                 // (128, 16)
    fused_hmma<<<grid, 128, SMEM_TOTAL>>>(Fn_dev, Wn_dev);

    finalize_rows<<<B / 8, 256>>>();
    finalize_out<<<1, 1024>>>((float*)d_out, B);
}

// round 8
// speedup vs baseline: 4.8190x; 1.1915x over previous
#include <cuda_runtime.h>
#include <cuda_bf16.h>
#include <math.h>
#include <cstdint>

// Problem constants: B=2048, C=16384, D=128
#define BDIM_MAX 2048
#define CDIM_MAX 16384
#define DDIM     128
#define NTAB     1024
#define VF       63.0f
#define V2F      3969.0f
#define L2E      1.4426950408889634f
#define MAGIC    12582912.0f           // 1.5 * 2^23

// -------- device scratch --------
__device__ __nv_bfloat16 g_Fn[BDIM_MAX * DDIM];   // normalized features (bf16)
__device__ __nv_bfloat16 g_Wn[CDIM_MAX * DDIM];   // normalized rows * k2 (bf16)
__device__ float  g_kq[CDIM_MAX];            // raw k2
__device__ float2 g_parC[CDIM_MAX];          // (Qh, ez)
__device__ float  g_Pu[BDIM_MAX];            // k1^2 * invh
__device__ float  g_a[BDIM_MAX];             // 2*k1 * invh
__device__ float  g_k1[BDIM_MAX];            // k1
__device__ float  g_xg[BDIM_MAX];            // gathered x at class y_b (exact fp32)
__device__ float  g_rowval[BDIM_MAX];
__device__ float  g_partial[BDIM_MAX * 256];
__device__ float2 g_tab[NTAB];
__device__ int    g_k1max_i = 0, g_k2max_i = 0;   // maxes idempotent across replays
__device__ float  g_invh;

// ---------------- helpers ----------------
__device__ __forceinline__ float f_exact(float t) {
    float s = sqrtf(t);
    return s - VF * logf(VF + s) - 0.5f * logf(s);
}

__device__ __forceinline__ uint32_t smem_u32(const void* p) {
    uint32_t a;
    asm("{ .reg .u64 t; cvta.to.shared.u64 t, %1; cvt.u32.u64 %0, t; }" : "=r"(a) : "l"(p));
    return a;
}

__device__ __forceinline__ void mma_bf16(float* d, const uint32_t* a, const uint32_t* b) {
    asm volatile(
        "mma.sync.aligned.m16n8k16.row.col.f32.bf16.bf16.f32 "
        "{%0,%1,%2,%3}, {%4,%5,%6,%7}, {%8,%9}, {%0,%1,%2,%3};\n"
        : "+f"(d[0]), "+f"(d[1]), "+f"(d[2]), "+f"(d[3])
        : "r"(a[0]), "r"(a[1]), "r"(a[2]), "r"(a[3]), "r"(b[0]), "r"(b[1]));
}

#define LDMX4(r0, r1, r2, r3, addr) \
    asm volatile("ldmatrix.sync.aligned.m8n8.x4.shared.b16 {%0,%1,%2,%3}, [%4];" \
        : "=r"(r0), "=r"(r1), "=r"(r2), "=r"(r3) : "r"(addr))

#define CPA16(dst, src) \
    asm volatile("cp.async.cg.shared.global [%0], [%1], 16;" :: "r"(dst), "l"(src))

__device__ __forceinline__ float ex2f(float y) {
    float r;
    asm("ex2.approx.f32 %0, %1;" : "=f"(r) : "f"(y));
    return r;
}

__device__ __forceinline__ uint32_t pack_bf2(float lo, float hi) {
    uint32_t r;
    asm("cvt.rn.bf16x2.f32 %0, %1, %2;" : "=r"(r) : "f"(hi), "f"(lo));
    return r;
}

// ---------------- prep: classes (warp each) + batch rows (half-block each) --
__global__ void prep(const float* __restrict__ W, const float* __restrict__ F,
                     const float* __restrict__ unc, const int* __restrict__ y,
                     int nClassBlocks) {
    if ((int)blockIdx.x < nClassBlocks) {
        // ---- class part: 8 classes per 256-thr block, one warp each ----
        int c = blockIdx.x * 8 + (threadIdx.x >> 5);
        int lane = threadIdx.x & 31;
        float4 w = ((const float4*)W)[c * 32 + lane];
        float ss = w.x*w.x + w.y*w.y + w.z*w.z + w.w*w.w;
        #pragma unroll
        for (int o = 16; o; o >>= 1) ss += __shfl_xor_sync(0xffffffffu, ss, o);
        float nw = sqrtf(ss);
        float k2 = fmaxf(nw, 1.0f) * 10.0f;       // INV_TEMP = 10
        float sc = k2 / nw;                       // fold k2 into operand
        uint2 pk;
        pk.x = pack_bf2(w.x * sc, w.y * sc);
        pk.y = pack_bf2(w.z * sc, w.w * sc);
        ((uint2*)g_Wn)[c * 32 + lane] = pk;
        if (lane == 0) {
            g_kq[c] = k2;
            atomicMax(&g_k2max_i, __float_as_int(k2));
        }
    } else {
        // ---- batch part: 2 rows per 256-thr block ----
        __shared__ float sred[2][12];
        __shared__ float s_invnb[2];
        int half = threadIdx.x >> 7;
        int t    = threadIdx.x & 127;
        int b    = (blockIdx.x - nClassBlocks) * 2 + half;
        int cls = y[b];
        float fv = F[b * DDIM + t];
        float wv = W[cls * DDIM + t];
        float ssf = fv * fv, ssw = wv * wv, dp = fv * wv;
        #pragma unroll
        for (int o = 16; o; o >>= 1) {
            ssf += __shfl_xor_sync(0xffffffffu, ssf, o);
            ssw += __shfl_xor_sync(0xffffffffu, ssw, o);
            dp  += __shfl_xor_sync(0xffffffffu, dp,  o);
        }
        int w = t >> 5, lane = t & 31;
        if (lane == 0) { sred[half][w] = ssf; sred[half][4 + w] = ssw; sred[half][8 + w] = dp; }
        __syncthreads();
        if (t == 0) {
            float sf = sred[half][0] + sred[half][1] + sred[half][2] + sred[half][3];
            float sw = sred[half][4] + sred[half][5] + sred[half][6] + sred[half][7];
            float dt = sred[half][8] + sred[half][9] + sred[half][10] + sred[half][11];
            float nb = sqrtf(sf), nw = sqrtf(sw);
            float k1 = 1.0f / unc[b];
            g_k1[b] = k1;
            float k2 = fmaxf(nw, 1.0f) * 10.0f;
            float dotn = dt / (nb * nw);
            float t3 = V2F + k1*k1 + k2*k2 + 2.0f*k1*k2*dotn;
            g_xg[b] = f_exact(t3) - f_exact(V2F + k2 * k2);
            atomicMax(&g_k1max_i, __float_as_int(k1));
            s_invnb[half] = 1.0f / nb;
        }
        __syncthreads();
        g_Fn[b * DDIM + t] = __float2bfloat16(fv * s_invnb[half]);
    }
}

// PWL table (analytic slope) + per-class float2 + per-row params
__global__ void params_table(int C, int B) {
    int i = blockIdx.x * 256 + threadIdx.x;
    float k1m = __int_as_float(g_k1max_i);
    float k2m = __int_as_float(g_k2max_i);
    float km  = k1m + k2m;
    float range = km * km + 16.0f;
    float h    = range / (float)(NTAB - 2);
    float invh = (float)(NTAB - 2) / range;
    float tlo2 = V2F - h;
    if (i == 0) g_invh = invh;
    if (i < NTAB) {
        float t0 = tlo2 + h * (float)i;
        float s0 = sqrtf(t0);
        float f0 = s0 - VF * logf(VF + s0) - 0.5f * logf(s0);
        float tm = t0 + 0.5f * h;
        float sm = sqrtf(tm);
        float fp = 1.0f / (2.0f * (VF + sm)) - 0.25f / tm;   // f'(t0 + h/2)
        g_tab[i] = make_float2(f0 * L2E, fp * h * L2E);
    }
    if (i < C) {
        float k2 = g_kq[i];
        g_parC[i] = make_float2((V2F + k2 * k2 - tlo2) * invh,
                                -f_exact(V2F + k2 * k2) * L2E);
    }
    if (i < B) {
        float k1 = g_k1[i];
        g_Pu[i] = k1 * k1 * invh;
        g_a[i]  = 2.0f * k1 * invh;
    }
}

// ---------------- fused bf16 HMMA GEMM + epilogue ----------------
// CTA: 128 threads (4 warps), tile 128(b) x 128(c), 2 CTAs/SM.
// Warp tile 64x64. K=128 in 2 chunks of 64 (bf16), double-buffered cp.async.
// Chunk layout: [128 rows][8 x 16B], ch' = ch ^ (row & 7).
#define OFF_PAR   0                        // 128 * float2 = 1024
#define OFF_TAB   1024                     // 8192
#define OFF_A     9216                     // 2 x 16384
#define OFF_B     41984                    // 2 x 16384
#define SMEM_TOTAL (41984 + 32768)         // 74752

__global__ void __launch_bounds__(128, 2)
fused_hmma(const __nv_bfloat16* __restrict__ Fn, const __nv_bfloat16* __restrict__ Wn) {
    extern __shared__ char smem[];
    const uint32_t sb = smem_u32(smem);
    float2* parS = (float2*)(smem + OFF_PAR);
    const float2* tab = (const float2*)(smem + OFF_TAB);

    const int tid = threadIdx.x;
    const int bx = blockIdx.x, by = blockIdx.y;
    const int wid = tid >> 5, lane = tid & 31;

    const __nv_bfloat16* gA = Fn + (size_t)by * 128 * 128;
    const __nv_bfloat16* gB = Wn + (size_t)bx * 128 * 128;
    const int prow = tid >> 3;          // 16 rows per pass
    const int pch  = tid & 7;

    // prefetch K-chunk c (64 bf16) into stage c
    #define PREFETCH(c) do {                                                        \
        uint32_t bufA = sb + OFF_A + (c) * 16384;                                   \
        uint32_t bufB = sb + OFF_B + (c) * 16384;                                   \
        _Pragma("unroll")                                                           \
        for (int i = 0; i < 8; ++i) {                                               \
            int row = i * 16 + prow;                                                \
            uint32_t so = row * 128 + (((uint32_t)(pch ^ (row & 7))) << 4);         \
            CPA16(bufA + so, gA + row * 128 + (c) * 64 + pch * 8);                  \
            CPA16(bufB + so, gB + row * 128 + (c) * 64 + pch * 8);                  \
        }                                                                           \
        asm volatile("cp.async.commit_group;" ::: "memory");                        \
    } while (0)

    PREFETCH(0);
    PREFETCH(1);

    // stage per-class params + table while prefetch is in flight
    {
        parS[tid] = g_parC[bx * 128 + tid];
        const float4* src = (const float4*)g_tab;
        float4* dst = (float4*)(smem + OFF_TAB);
        #pragma unroll
        for (int i = 0; i < 4; ++i) dst[i * 128 + tid] = src[i * 128 + tid];
    }

    const int warp_m = wid >> 1, warp_n = wid & 1;
    const int g = lane >> 2, kl = lane & 3;
    const int sel = lane >> 3;

    // ldmatrix bases: A x4 = {rows, rows+8} x {k0-7, k8-15}; B x4 = {n, n+8} x {k0-7, k8-15}
    uint32_t offA[4], rm7A[4];
    const uint32_t csA = sel >> 1;           // 16B step within 32B k-slice
    #pragma unroll
    for (int mt = 0; mt < 4; ++mt) {
        int row = warp_m * 64 + mt * 16 + (sel & 1) * 8 + (lane & 7);
        offA[mt] = row * 128;
        rm7A[mt] = row & 7;
    }
    uint32_t offB[4], rm7B[4];
    const uint32_t csB = sel & 1;
    #pragma unroll
    for (int p = 0; p < 4; ++p) {
        int row = warp_n * 64 + p * 16 + (sel >> 1) * 8 + (lane & 7);
        offB[p] = row * 128;
        rm7B[p] = row & 7;
    }

    float acc[4][8][4];
    #pragma unroll
    for (int mt = 0; mt < 4; ++mt)
        #pragma unroll
        for (int nt = 0; nt < 8; ++nt)
            #pragma unroll
            for (int q = 0; q < 4; ++q) acc[mt][nt][q] = 0.0f;

    #pragma unroll
    for (int c = 0; c < 2; ++c) {
        if (c == 0) asm volatile("cp.async.wait_group 1;" ::: "memory");
        else        asm volatile("cp.async.wait_group 0;" ::: "memory");
        __syncthreads();

        uint32_t bufA = sb + OFF_A + c * 16384;
        uint32_t bufB = sb + OFF_B + c * 16384;
        #pragma unroll
        for (int kc = 0; kc < 4; ++kc) {           // 4 k-steps of K=16 bf16
            uint32_t a[4][4], b[8][2];
            #pragma unroll
            for (int mt = 0; mt < 4; ++mt) {
                uint32_t ad = bufA + offA[mt]
                            + ((((uint32_t)(2 * kc) + csA) ^ rm7A[mt]) << 4);
                LDMX4(a[mt][0], a[mt][1], a[mt][2], a[mt][3], ad);
            }
            #pragma unroll
            for (int p = 0; p < 4; ++p) {
                uint32_t bd = bufB + offB[p]
                            + ((((uint32_t)(2 * kc) + csB) ^ rm7B[p]) << 4);
                LDMX4(b[2*p][0], b[2*p][1], b[2*p+1][0], b[2*p+1][1], bd);
            }
            #pragma unroll
            for (int mt = 0; mt < 4; ++mt)
                #pragma unroll
                for (int nt = 0; nt < 8; ++nt)
                    mma_bf16(acc[mt][nt], a[mt], b[nt]);
        }
    }

    // ---- epilogue ----
    float Pu[4][2], ar[4][2];
    #pragma unroll
    for (int mt = 0; mt < 4; ++mt)
        #pragma unroll
        for (int h = 0; h < 2; ++h) {
            int r = by * 128 + warp_m * 64 + mt * 16 + h * 8 + g;
            Pu[mt][h] = g_Pu[r];
            ar[mt][h] = g_a[r];
        }

    float rsum[4][2];
    #pragma unroll
    for (int mt = 0; mt < 4; ++mt) { rsum[mt][0] = 0.0f; rsum[mt][1] = 0.0f; }

    #pragma unroll
    for (int nt = 0; nt < 8; ++nt) {
        #pragma unroll
        for (int q = 0; q < 2; ++q) {
            int col = warp_n * 64 + nt * 8 + 2 * kl + q;
            float2 pe = parS[col];                 // (Qh, ez)
            #pragma unroll
            for (int mt = 0; mt < 4; ++mt)
                #pragma unroll
                for (int h = 0; h < 2; ++h) {
                    float dot2 = acc[mt][nt][h * 2 + q];      // k2 * cos
                    float u  = fmaf(ar[mt][h], dot2, Pu[mt][h] + pe.x);
                    float rB = u + MAGIC;
                    int   k  = __float_as_int(rB) - 0x4B400000;  // round(u)
                    float fr = u - (rB - MAGIC);                 // [-0.5, 0.5]
                    float2 te = tab[k];
                    float y  = fmaf(fr, te.y, te.x) + pe.y;      // log2 exp arg
                    rsum[mt][h] += ex2f(y);
                }
        }
    }

    #pragma unroll
    for (int mt = 0; mt < 4; ++mt)
        #pragma unroll
        for (int h = 0; h < 2; ++h) {
            float s = rsum[mt][h];
            s += __shfl_xor_sync(0xffffffffu, s, 1);
            s += __shfl_xor_sync(0xffffffffu, s, 2);
            if (kl == 0) {
                int r = by * 128 + warp_m * 64 + mt * 16 + h * 8 + g;
                g_partial[(size_t)r * 256 + bx * 2 + warp_n] = s;
            }
        }
}

// ---------------- final reduction (2-stage, parallel) ----------------
__global__ void finalize_rows() {
    int r = blockIdx.x * 8 + (threadIdx.x >> 5);
    int lane = threadIdx.x & 31;
    const float4* p4 = (const float4*)(g_partial + (size_t)r * 256);
    float4 v0 = p4[lane], v1 = p4[lane + 32];
    float S = (v0.x + v0.y) + (v0.z + v0.w) + (v1.x + v1.y) + (v1.z + v1.w);
    #pragma unroll
    for (int o = 16; o; o >>= 1) S += __shfl_xor_sync(0xffffffffu, S, o);
    if (lane == 0) g_rowval[r] = logf(S) - g_xg[r];
}

__global__ void finalize_out(float* __restrict__ out, int B) {
    __shared__ float sred[32];
    int t = threadIdx.x;
    float local = g_rowval[t] + g_rowval[t + 1024];
    #pragma unroll
    for (int o = 16; o; o >>= 1) local += __shfl_xor_sync(0xffffffffu, local, o);
    if ((t & 31) == 0) sred[t >> 5] = local;
    __syncthreads();
    if (t < 32) {
        float v = sred[t];
        #pragma unroll
        for (int o = 16; o; o >>= 1) v += __shfl_xor_sync(0xffffffffu, v, o);
        if (t == 0) out[0] = v / (float)B;
    }
}

// ---------------- launch ----------------
extern "C" void kernel_launch(void* const* d_in, const int* in_sizes, int n_in,
                              void* d_out, int out_size) {
    // inputs: [0]=pred (UNUSED), [1]=unc, [2]=y, [3]=features, [4]=classifier_weight
    const float* unc = (const float*)d_in[1];
    const int*   y   = (const int*)d_in[2];
    const float* F   = (const float*)d_in[3];
    const float* W   = (const float*)d_in[4];
    int B = in_sizes[1];
    int C = in_sizes[4] / DDIM;

    int nClassBlocks = C / 8;
    prep<<<nClassBlocks + B / 2, 256>>>(W, F, unc, y, nClassBlocks);
    params_table<<<(C + 255) / 256, 256>>>(C, B);

    static __nv_bfloat16* Fn_dev = nullptr;
    static __nv_bfloat16* Wn_dev = nullptr;
    if (!Fn_dev) {
        cudaGetSymbolAddress((void**)&Fn_dev, g_Fn);
        cudaGetSymbolAddress((void**)&Wn_dev, g_Wn);
        cudaFuncSetAttribute(fused_hmma, cudaFuncAttributeMaxDynamicSharedMemorySize, SMEM_TOTAL);
    }

    dim3 grid(C / 128, B / 128);                 // (128, 16)
    fused_hmma<<<grid, 128, SMEM_TOTAL>>>(Fn_dev, Wn_dev);

    finalize_rows<<<B / 8, 256>>>();
    finalize_out<<<1, 1024>>>((float*)d_out, B);
}